// round 1
// baseline (speedup 1.0000x reference)
#include <cuda_runtime.h>
#include <cuda_bf16.h>
#include <cstdint>

// Problem constants
#define BATCH 4
#define TSEQ  2048
#define CDIM  1024
#define NHEAD 16
#define HDIM  64
#define C3    (3*CDIM)

// Scratch: QKV (B*T x 3C) and Y (B*T x C), device globals (no allocation allowed)
__device__ float g_qkv[(size_t)BATCH * TSEQ * C3];
__device__ float g_y[(size_t)BATCH * TSEQ * CDIM];

// ---------------------------------------------------------------------------
// Tiled SGEMM: C = A(MxK) * B(KxN), row-major, all dims multiples of tile sizes
// ---------------------------------------------------------------------------
#define BM 128
#define BN 128
#define BK 16
#define TM 8
#define TN 8

__global__ void __launch_bounds__(256) sgemm_kernel(
    const float* __restrict__ A, const float* __restrict__ B,
    float* __restrict__ C, int M, int N, int K)
{
    __shared__ float As[BK][BM];
    __shared__ float Bs[BK][BN];

    const int tid = threadIdx.x;
    const int bm  = blockIdx.y * BM;
    const int bn  = blockIdx.x * BN;

    // A tile loads: 128x16 = 2048 floats = 512 float4 -> 2 per thread
    const int arow = tid >> 2;          // 0..63 (+64)
    const int acol = (tid & 3) * 4;     // 0,4,8,12
    // B tile loads: 16x128 = 2048 floats -> 2 per thread
    const int brow = tid >> 5;          // 0..7 (+8)
    const int bcol = (tid & 31) * 4;    // 0..124

    const int tm0 = (tid >> 4) * TM;    // 16x16 thread grid
    const int tn0 = (tid & 15) * TN;

    float acc[TM][TN];
    #pragma unroll
    for (int i = 0; i < TM; i++)
        #pragma unroll
        for (int j = 0; j < TN; j++) acc[i][j] = 0.f;

    for (int k0 = 0; k0 < K; k0 += BK) {
        #pragma unroll
        for (int i = 0; i < 2; i++) {
            int r = arow + i * 64;
            float4 v = *(const float4*)&A[(size_t)(bm + r) * K + k0 + acol];
            As[acol + 0][r] = v.x;
            As[acol + 1][r] = v.y;
            As[acol + 2][r] = v.z;
            As[acol + 3][r] = v.w;
        }
        #pragma unroll
        for (int i = 0; i < 2; i++) {
            int r = brow + i * 8;
            *(float4*)&Bs[r][bcol] = *(const float4*)&B[(size_t)(k0 + r) * N + bn + bcol];
        }
        __syncthreads();

        #pragma unroll
        for (int k = 0; k < BK; k++) {
            float ar[TM], br[TN];
            #pragma unroll
            for (int i = 0; i < TM; i++) ar[i] = As[k][tm0 + i];
            #pragma unroll
            for (int j = 0; j < TN; j++) br[j] = Bs[k][tn0 + j];
            #pragma unroll
            for (int i = 0; i < TM; i++)
                #pragma unroll
                for (int j = 0; j < TN; j++)
                    acc[i][j] += ar[i] * br[j];
        }
        __syncthreads();
    }

    const int cr0 = bm + tm0;
    const int cc0 = bn + tn0;
    #pragma unroll
    for (int i = 0; i < TM; i++) {
        #pragma unroll
        for (int j = 0; j < TN; j += 4) {
            float4 v = make_float4(acc[i][j], acc[i][j+1], acc[i][j+2], acc[i][j+3]);
            *(float4*)&C[(size_t)(cr0 + i) * N + cc0 + j] = v;
        }
    }
}

// ---------------------------------------------------------------------------
// Flash attention (causal), fp32, Br=Bc=64, D=64
// grid: (qt=32, h=16, b=4), 256 threads (16x16), 4x4 register tiles
// ---------------------------------------------------------------------------
#define QPAD 65   // 64 + 1 padding

__global__ void __launch_bounds__(256) flash_kernel(
    const float* __restrict__ qkv, float* __restrict__ y)
{
    extern __shared__ float sm[];
    float* Qs = sm;                  // 64 x 65
    float* Ks = Qs + 64 * QPAD;      // 64 x 65
    float* Vs = Ks + 64 * QPAD;      // 64 x 65
    float* Ss = Vs + 64 * QPAD;      // 64 x 64

    const int b  = blockIdx.z;
    const int h  = blockIdx.y;
    const int qt = blockIdx.x;
    const int tid = threadIdx.x;
    const int ty = tid >> 4;        // 0..15
    const int tx = tid & 15;        // 0..15

    const float scale = 0.125f;     // 1/sqrt(64)
    const float* base = qkv + (size_t)b * TSEQ * C3 + (size_t)h * HDIM;

    // Load Q tile (rows qt*64 .. qt*64+63)
    #pragma unroll
    for (int i = 0; i < 4; i++) {
        int vi = i * 256 + tid;           // 0..1023 float4s
        int r  = vi >> 4;
        int c4 = (vi & 15) * 4;
        float4 v = *(const float4*)&base[(size_t)(qt * 64 + r) * C3 + c4];
        Qs[r * QPAD + c4 + 0] = v.x;
        Qs[r * QPAD + c4 + 1] = v.y;
        Qs[r * QPAD + c4 + 2] = v.z;
        Qs[r * QPAD + c4 + 3] = v.w;
    }

    float m_i[4], l_i[4], o[4][4];
    #pragma unroll
    for (int i = 0; i < 4; i++) {
        m_i[i] = -1e30f; l_i[i] = 0.f;
        #pragma unroll
        for (int j = 0; j < 4; j++) o[i][j] = 0.f;
    }

    for (int kb = 0; kb <= qt; kb++) {
        __syncthreads();   // previous iter done with Ks/Vs/Ss (and Q loaded on 1st iter)

        // Load K, V tiles (rows kb*64 ..)
        #pragma unroll
        for (int i = 0; i < 4; i++) {
            int vi = i * 256 + tid;
            int r  = vi >> 4;
            int c4 = (vi & 15) * 4;
            const float* rowp = &base[(size_t)(kb * 64 + r) * C3];
            float4 kv = *(const float4*)&rowp[CDIM + c4];
            float4 vv = *(const float4*)&rowp[2 * CDIM + c4];
            Ks[r * QPAD + c4 + 0] = kv.x; Ks[r * QPAD + c4 + 1] = kv.y;
            Ks[r * QPAD + c4 + 2] = kv.z; Ks[r * QPAD + c4 + 3] = kv.w;
            Vs[r * QPAD + c4 + 0] = vv.x; Vs[r * QPAD + c4 + 1] = vv.y;
            Vs[r * QPAD + c4 + 2] = vv.z; Vs[r * QPAD + c4 + 3] = vv.w;
        }
        __syncthreads();

        // S = Q K^T (4x4 per thread)
        float s[4][4];
        #pragma unroll
        for (int i = 0; i < 4; i++)
            #pragma unroll
            for (int j = 0; j < 4; j++) s[i][j] = 0.f;

        #pragma unroll 8
        for (int d = 0; d < 64; d++) {
            float qv[4], kv[4];
            #pragma unroll
            for (int i = 0; i < 4; i++) qv[i] = Qs[(ty * 4 + i) * QPAD + d];
            #pragma unroll
            for (int j = 0; j < 4; j++) kv[j] = Ks[(tx * 4 + j) * QPAD + d];
            #pragma unroll
            for (int i = 0; i < 4; i++)
                #pragma unroll
                for (int j = 0; j < 4; j++)
                    s[i][j] += qv[i] * kv[j];
        }

        const int qrow0 = qt * 64 + ty * 4;
        const int kcol0 = kb * 64 + tx * 4;
        const bool diag = (kb == qt);

        // scale + causal mask
        #pragma unroll
        for (int i = 0; i < 4; i++)
            #pragma unroll
            for (int j = 0; j < 4; j++) {
                s[i][j] *= scale;
                if (diag && (kcol0 + j > qrow0 + i)) s[i][j] = -1e30f;
            }

        // online softmax per row (reduce across 16 tx lanes, width-16 shfl)
        #pragma unroll
        for (int i = 0; i < 4; i++) {
            float mt = fmaxf(fmaxf(s[i][0], s[i][1]), fmaxf(s[i][2], s[i][3]));
            #pragma unroll
            for (int off = 8; off >= 1; off >>= 1)
                mt = fmaxf(mt, __shfl_xor_sync(0xffffffffu, mt, off, 16));
            float mn = fmaxf(m_i[i], mt);
            float corr = __expf(m_i[i] - mn);
            m_i[i] = mn;
            float rs = 0.f;
            #pragma unroll
            for (int j = 0; j < 4; j++) {
                s[i][j] = __expf(s[i][j] - mn);
                rs += s[i][j];
            }
            #pragma unroll
            for (int off = 8; off >= 1; off >>= 1)
                rs += __shfl_xor_sync(0xffffffffu, rs, off, 16);
            l_i[i] = l_i[i] * corr + rs;
            #pragma unroll
            for (int j = 0; j < 4; j++) o[i][j] *= corr;
        }

        // write P to shared
        #pragma unroll
        for (int i = 0; i < 4; i++)
            #pragma unroll
            for (int j = 0; j < 4; j++)
                Ss[(ty * 4 + i) * 64 + tx * 4 + j] = s[i][j];
        __syncthreads();

        // O += P * V
        #pragma unroll 8
        for (int c = 0; c < 64; c++) {
            float pv[4], vv[4];
            #pragma unroll
            for (int i = 0; i < 4; i++) pv[i] = Ss[(ty * 4 + i) * 64 + c];
            #pragma unroll
            for (int j = 0; j < 4; j++) vv[j] = Vs[c * QPAD + tx * 4 + j];
            #pragma unroll
            for (int i = 0; i < 4; i++)
                #pragma unroll
                for (int j = 0; j < 4; j++)
                    o[i][j] += pv[i] * vv[j];
        }
    }

    // epilogue: normalize and write to y (B,T,C) at column h*64 + ...
    #pragma unroll
    for (int i = 0; i < 4; i++) {
        float inv = 1.0f / l_i[i];
        int t = qt * 64 + ty * 4 + i;
        float* dst = &g_y[((size_t)b * TSEQ + t) * CDIM + h * HDIM + tx * 4];
        float4 v = make_float4(o[i][0] * inv, o[i][1] * inv, o[i][2] * inv, o[i][3] * inv);
        *(float4*)dst = v;
    }
    (void)y;
}

// ---------------------------------------------------------------------------
extern "C" void kernel_launch(void* const* d_in, const int* in_sizes, int n_in,
                              void* d_out, int out_size)
{
    const float* x      = (const float*)d_in[0];   // (4,2048,1024)
    const float* w_qkv  = (const float*)d_in[1];   // (1024,3072)
    const float* w_proj = (const float*)d_in[2];   // (1024,1024)
    float* out = (float*)d_out;                    // (4,2048,1024)

    float* qkv; cudaGetSymbolAddress((void**)&qkv, g_qkv);
    float* yb;  cudaGetSymbolAddress((void**)&yb,  g_y);

    const int M = BATCH * TSEQ;  // 8192

    // 1) QKV = X @ W_qkv   (8192 x 3072, K=1024)
    {
        dim3 grid(C3 / BN, M / BM);
        sgemm_kernel<<<grid, 256>>>(x, w_qkv, qkv, M, C3, CDIM);
    }

    // 2) Flash attention -> g_y
    {
        size_t smem = (3 * 64 * QPAD + 64 * 64) * sizeof(float);   // ~66 KB
        cudaFuncSetAttribute(flash_kernel, cudaFuncAttributeMaxDynamicSharedMemorySize, (int)smem);
        dim3 grid(TSEQ / 64, NHEAD, BATCH);
        flash_kernel<<<grid, 256, smem>>>(qkv, yb);
    }

    // 3) OUT = Y @ W_proj  (8192 x 1024, K=1024)
    {
        dim3 grid(CDIM / BN, M / BM);
        sgemm_kernel<<<grid, 256>>>(yb, w_proj, out, M, CDIM, CDIM);
    }
    (void)in_sizes; (void)n_in; (void)out_size;
}

// round 3
// speedup vs baseline: 1.4721x; 1.4721x over previous
#include <cuda_runtime.h>
#include <cuda_bf16.h>
#include <cstdint>

// Problem constants
#define BATCH 4
#define TSEQ  2048
#define CDIM  1024
#define NHEAD 16
#define HDIM  64
#define C3    (3*CDIM)
#define MTOT  (BATCH*TSEQ)   // 8192

// ---------------------------------------------------------------------------
// Device-global scratch (no allocation allowed)
// ---------------------------------------------------------------------------
__device__ __align__(256) float g_qkv[(size_t)MTOT * C3];
__device__ __align__(256) float g_y[(size_t)MTOT * CDIM];
__device__ __align__(256) __nv_bfloat16 g_xh[(size_t)MTOT * CDIM];
__device__ __align__(256) __nv_bfloat16 g_xl[(size_t)MTOT * CDIM];
__device__ __align__(256) __nv_bfloat16 g_yh[(size_t)MTOT * CDIM];
__device__ __align__(256) __nv_bfloat16 g_yl[(size_t)MTOT * CDIM];
__device__ __align__(256) __nv_bfloat16 g_wqh[(size_t)C3 * CDIM];   // transposed: N x K
__device__ __align__(256) __nv_bfloat16 g_wql[(size_t)C3 * CDIM];
__device__ __align__(256) __nv_bfloat16 g_wph[(size_t)CDIM * CDIM];
__device__ __align__(256) __nv_bfloat16 g_wpl[(size_t)CDIM * CDIM];

// ---------------------------------------------------------------------------
// Helpers (baseline PTX only — no 'a'-gated instructions)
// ---------------------------------------------------------------------------
__device__ __forceinline__ uint32_t smem_u32(const void* p) {
    uint32_t a;
    asm("{ .reg .u64 t; cvta.to.shared.u64 t, %1; cvt.u32.u64 %0, t; }" : "=r"(a) : "l"(p));
    return a;
}
__device__ __forceinline__ void cpa16(uint32_t dst, const void* src) {
    asm volatile("cp.async.cg.shared.global [%0], [%1], 16;\n" :: "r"(dst), "l"(src));
}
#define CP_COMMIT() asm volatile("cp.async.commit_group;\n" ::: "memory")
#define CP_WAIT(n)  asm volatile("cp.async.wait_group %0;\n" :: "n"(n) : "memory")

__device__ __forceinline__ void ldsm4(uint32_t addr, uint32_t* r) {
    asm volatile("ldmatrix.sync.aligned.m8n8.x4.shared.b16 {%0,%1,%2,%3}, [%4];"
                 : "=r"(r[0]), "=r"(r[1]), "=r"(r[2]), "=r"(r[3]) : "r"(addr));
}
__device__ __forceinline__ void mma16816(float* d, const uint32_t* a, uint32_t b0, uint32_t b1) {
    asm volatile("mma.sync.aligned.m16n8k16.row.col.f32.bf16.bf16.f32 "
                 "{%0,%1,%2,%3},{%4,%5,%6,%7},{%8,%9},{%0,%1,%2,%3};"
                 : "+f"(d[0]), "+f"(d[1]), "+f"(d[2]), "+f"(d[3])
                 : "r"(a[0]), "r"(a[1]), "r"(a[2]), "r"(a[3]), "r"(b0), "r"(b1));
}

// ---------------------------------------------------------------------------
// Split fp32 -> bf16 hi/lo
// ---------------------------------------------------------------------------
__global__ void __launch_bounds__(256) split_kernel(
    const float* __restrict__ in, __nv_bfloat16* __restrict__ hi,
    __nv_bfloat16* __restrict__ lo, int n4)
{
    int i = blockIdx.x * 256 + threadIdx.x;
    if (i >= n4) return;
    float4 v = ((const float4*)in)[i];
    float vv[4] = {v.x, v.y, v.z, v.w};
    __nv_bfloat16 h[4], l[4];
    #pragma unroll
    for (int j = 0; j < 4; j++) {
        h[j] = __float2bfloat16(vv[j]);
        l[j] = __float2bfloat16(vv[j] - __bfloat162float(h[j]));
    }
    __nv_bfloat162 h01, h23, l01, l23;
    h01.x = h[0]; h01.y = h[1]; h23.x = h[2]; h23.y = h[3];
    l01.x = l[0]; l01.y = l[1]; l23.x = l[2]; l23.y = l[3];
    ((__nv_bfloat162*)hi)[2*i]   = h01;
    ((__nv_bfloat162*)hi)[2*i+1] = h23;
    ((__nv_bfloat162*)lo)[2*i]   = l01;
    ((__nv_bfloat162*)lo)[2*i+1] = l23;
}

// ---------------------------------------------------------------------------
// Transpose + split weights: W (KxN fp32, row-major) -> Wt_hi/lo (NxK bf16)
// ---------------------------------------------------------------------------
__global__ void __launch_bounds__(256) tsplit_kernel(
    const float* __restrict__ W, __nv_bfloat16* __restrict__ Th,
    __nv_bfloat16* __restrict__ Tl, int K, int N)
{
    __shared__ float t[32][33];
    int n0 = blockIdx.x * 32, k0 = blockIdx.y * 32;
    int tx = threadIdx.x, ty = threadIdx.y;   // 32 x 8
    #pragma unroll
    for (int i = 0; i < 32; i += 8)
        t[ty + i][tx] = W[(size_t)(k0 + ty + i) * N + n0 + tx];
    __syncthreads();
    #pragma unroll
    for (int i = 0; i < 32; i += 8) {
        float v = t[tx][ty + i];
        __nv_bfloat16 h = __float2bfloat16(v);
        __nv_bfloat16 l = __float2bfloat16(v - __bfloat162float(h));
        size_t o = (size_t)(n0 + ty + i) * K + k0 + tx;
        Th[o] = h; Tl[o] = l;
    }
}

// ---------------------------------------------------------------------------
// mma.sync 3xBF16 GEMM: C(MxN) = A(MxK) * B(NxK)^T
// Tile 128x128, BK=32, 8 warps (2M x 4N, each 64x32), cp.async double buffer.
// smem rows padded to 40 bf16 (80B) -> conflict-free ldmatrix.
// ---------------------------------------------------------------------------
#define TROW_B     80                    // bytes per padded row
#define TILE_B     (128 * TROW_B)        // 10240 B per tile
#define STAGE_B    (4 * TILE_B)          // Ah, Al, Bh, Bl
#define MM_SMEM    (2 * STAGE_B)         // 81920 B

__global__ void __launch_bounds__(256) mmasync_kernel(
    const __nv_bfloat16* __restrict__ Ah, const __nv_bfloat16* __restrict__ Al,
    const __nv_bfloat16* __restrict__ Bh, const __nv_bfloat16* __restrict__ Bl,
    float* __restrict__ C, int N, int K)
{
    extern __shared__ char smraw[];
    const uint32_t smb = smem_u32(smraw);

    const int tid  = threadIdx.x;
    const int wid  = tid >> 5, lane = tid & 31;
    const int wm   = wid & 1;          // 0..1  (M)
    const int wn   = wid >> 1;         // 0..3  (N)
    const int bm   = blockIdx.y * 128, bn = blockIdx.x * 128;
    const int l16  = lane & 15, lh = lane >> 4;

    float acc[4][4][4];
    #pragma unroll
    for (int i = 0; i < 4; i++)
        #pragma unroll
        for (int j = 0; j < 4; j++)
            #pragma unroll
            for (int k = 0; k < 4; k++) acc[i][j][k] = 0.f;

    const __nv_bfloat16* srcs[4] = {Ah, Al, Bh, Bl};

    // fill one stage: 4 tiles x 128 rows x 2 chunks(16B)/thread
    auto fill = [&](int s, int k0) {
        uint32_t sb = smb + (uint32_t)s * STAGE_B;
        #pragma unroll
        for (int t = 0; t < 4; t++) {
            const __nv_bfloat16* src = srcs[t];
            const int rbase = (t < 2) ? bm : bn;
            uint32_t tb = sb + (uint32_t)t * TILE_B;
            #pragma unroll
            for (int i = 0; i < 2; i++) {
                int chunk = tid + i * 256;       // 0..511
                int row = chunk >> 2, c = chunk & 3;
                cpa16(tb + (uint32_t)(row * TROW_B + c * 16),
                      src + (size_t)(rbase + row) * K + k0 + c * 8);
            }
        }
    };

    const int nch = K >> 5;   // BK = 32
    fill(0, 0); CP_COMMIT();

    for (int i = 0; i < nch; i++) {
        if (i + 1 < nch) { fill((i + 1) & 1, (i + 1) << 5); CP_COMMIT(); CP_WAIT(1); }
        else             { CP_WAIT(0); }
        __syncthreads();

        uint32_t sb = smb + (uint32_t)(i & 1) * STAGE_B;
        uint32_t Abh = sb, Abl = sb + TILE_B, Bbh = sb + 2 * TILE_B, Bbl = sb + 3 * TILE_B;

        #pragma unroll
        for (int kh = 0; kh < 2; kh++) {
            const uint32_t koff = (uint32_t)(kh * 32 + lh * 16);
            uint32_t ah[4][4], al[4][4];
            #pragma unroll
            for (int mt = 0; mt < 4; mt++) {
                uint32_t ro = (uint32_t)((wm * 64 + mt * 16 + l16) * TROW_B) + koff;
                ldsm4(Abh + ro, ah[mt]);
                ldsm4(Abl + ro, al[mt]);
            }
            uint32_t bh[2][4], bl[2][4];
            #pragma unroll
            for (int np = 0; np < 2; np++) {
                uint32_t ro = (uint32_t)((wn * 32 + np * 16 + l16) * TROW_B) + koff;
                ldsm4(Bbh + ro, bh[np]);
                ldsm4(Bbl + ro, bl[np]);
            }
            #pragma unroll
            for (int mt = 0; mt < 4; mt++)
                #pragma unroll
                for (int nt = 0; nt < 4; nt++) {
                    const int np = nt >> 1, o = nt & 1;
                    mma16816(acc[mt][nt], ah[mt], bh[np][o], bh[np][o + 2]);
                    mma16816(acc[mt][nt], ah[mt], bl[np][o], bl[np][o + 2]);
                    mma16816(acc[mt][nt], al[mt], bh[np][o], bh[np][o + 2]);
                }
        }
        __syncthreads();
    }

    // Epilogue: d0,d1 -> (row, col..col+1); d2,d3 -> (row+8, col..col+1)
    const int er = lane >> 2, ec = (lane & 3) * 2;
    #pragma unroll
    for (int mt = 0; mt < 4; mt++)
        #pragma unroll
        for (int nt = 0; nt < 4; nt++) {
            int r0 = bm + wm * 64 + mt * 16 + er;
            int c0 = bn + wn * 32 + nt * 8 + ec;
            float2 v0 = make_float2(acc[mt][nt][0], acc[mt][nt][1]);
            float2 v1 = make_float2(acc[mt][nt][2], acc[mt][nt][3]);
            *(float2*)&C[(size_t)r0 * N + c0]       = v0;
            *(float2*)&C[(size_t)(r0 + 8) * N + c0] = v1;
        }
}

// ---------------------------------------------------------------------------
// Flash attention (causal), fp32, Br=Bc=64, D=64
// ---------------------------------------------------------------------------
#define QPAD 65

__global__ void __launch_bounds__(256) flash_kernel(
    const float* __restrict__ qkv, float* __restrict__ y)
{
    extern __shared__ float sm[];
    float* Qs = sm;
    float* Ks = Qs + 64 * QPAD;
    float* Vs = Ks + 64 * QPAD;
    float* Ss = Vs + 64 * QPAD;

    const int b  = blockIdx.z;
    const int h  = blockIdx.y;
    const int qt = blockIdx.x;
    const int tid = threadIdx.x;
    const int ty = tid >> 4;
    const int tx = tid & 15;

    const float scale = 0.125f;
    const float* base = qkv + (size_t)b * TSEQ * C3 + (size_t)h * HDIM;

    #pragma unroll
    for (int i = 0; i < 4; i++) {
        int vi = i * 256 + tid;
        int r  = vi >> 4;
        int c4 = (vi & 15) * 4;
        float4 v = *(const float4*)&base[(size_t)(qt * 64 + r) * C3 + c4];
        Qs[r * QPAD + c4 + 0] = v.x;
        Qs[r * QPAD + c4 + 1] = v.y;
        Qs[r * QPAD + c4 + 2] = v.z;
        Qs[r * QPAD + c4 + 3] = v.w;
    }

    float m_i[4], l_i[4], o[4][4];
    #pragma unroll
    for (int i = 0; i < 4; i++) {
        m_i[i] = -1e30f; l_i[i] = 0.f;
        #pragma unroll
        for (int j = 0; j < 4; j++) o[i][j] = 0.f;
    }

    for (int kb = 0; kb <= qt; kb++) {
        __syncthreads();
        #pragma unroll
        for (int i = 0; i < 4; i++) {
            int vi = i * 256 + tid;
            int r  = vi >> 4;
            int c4 = (vi & 15) * 4;
            const float* rowp = &base[(size_t)(kb * 64 + r) * C3];
            float4 kv = *(const float4*)&rowp[CDIM + c4];
            float4 vv = *(const float4*)&rowp[2 * CDIM + c4];
            Ks[r * QPAD + c4 + 0] = kv.x; Ks[r * QPAD + c4 + 1] = kv.y;
            Ks[r * QPAD + c4 + 2] = kv.z; Ks[r * QPAD + c4 + 3] = kv.w;
            Vs[r * QPAD + c4 + 0] = vv.x; Vs[r * QPAD + c4 + 1] = vv.y;
            Vs[r * QPAD + c4 + 2] = vv.z; Vs[r * QPAD + c4 + 3] = vv.w;
        }
        __syncthreads();

        float s[4][4];
        #pragma unroll
        for (int i = 0; i < 4; i++)
            #pragma unroll
            for (int j = 0; j < 4; j++) s[i][j] = 0.f;

        #pragma unroll 8
        for (int d = 0; d < 64; d++) {
            float qv[4], kv[4];
            #pragma unroll
            for (int i = 0; i < 4; i++) qv[i] = Qs[(ty * 4 + i) * QPAD + d];
            #pragma unroll
            for (int j = 0; j < 4; j++) kv[j] = Ks[(tx * 4 + j) * QPAD + d];
            #pragma unroll
            for (int i = 0; i < 4; i++)
                #pragma unroll
                for (int j = 0; j < 4; j++)
                    s[i][j] += qv[i] * kv[j];
        }

        const int qrow0 = qt * 64 + ty * 4;
        const int kcol0 = kb * 64 + tx * 4;
        const bool diag = (kb == qt);

        #pragma unroll
        for (int i = 0; i < 4; i++)
            #pragma unroll
            for (int j = 0; j < 4; j++) {
                s[i][j] *= scale;
                if (diag && (kcol0 + j > qrow0 + i)) s[i][j] = -1e30f;
            }

        #pragma unroll
        for (int i = 0; i < 4; i++) {
            float mt = fmaxf(fmaxf(s[i][0], s[i][1]), fmaxf(s[i][2], s[i][3]));
            #pragma unroll
            for (int off = 8; off >= 1; off >>= 1)
                mt = fmaxf(mt, __shfl_xor_sync(0xffffffffu, mt, off, 16));
            float mn = fmaxf(m_i[i], mt);
            float corr = __expf(m_i[i] - mn);
            m_i[i] = mn;
            float rs = 0.f;
            #pragma unroll
            for (int j = 0; j < 4; j++) {
                s[i][j] = __expf(s[i][j] - mn);
                rs += s[i][j];
            }
            #pragma unroll
            for (int off = 8; off >= 1; off >>= 1)
                rs += __shfl_xor_sync(0xffffffffu, rs, off, 16);
            l_i[i] = l_i[i] * corr + rs;
            #pragma unroll
            for (int j = 0; j < 4; j++) o[i][j] *= corr;
        }

        #pragma unroll
        for (int i = 0; i < 4; i++)
            #pragma unroll
            for (int j = 0; j < 4; j++)
                Ss[(ty * 4 + i) * 64 + tx * 4 + j] = s[i][j];
        __syncthreads();

        #pragma unroll 8
        for (int c = 0; c < 64; c++) {
            float pv[4], vv[4];
            #pragma unroll
            for (int i = 0; i < 4; i++) pv[i] = Ss[(ty * 4 + i) * 64 + c];
            #pragma unroll
            for (int j = 0; j < 4; j++) vv[j] = Vs[c * QPAD + tx * 4 + j];
            #pragma unroll
            for (int i = 0; i < 4; i++)
                #pragma unroll
                for (int j = 0; j < 4; j++)
                    o[i][j] += pv[i] * vv[j];
        }
    }

    #pragma unroll
    for (int i = 0; i < 4; i++) {
        float inv = 1.0f / l_i[i];
        int t = qt * 64 + ty * 4 + i;
        float* dst = &g_y[((size_t)b * TSEQ + t) * CDIM + h * HDIM + tx * 4];
        float4 v = make_float4(o[i][0] * inv, o[i][1] * inv, o[i][2] * inv, o[i][3] * inv);
        *(float4*)dst = v;
    }
    (void)y;
}

// ---------------------------------------------------------------------------
extern "C" void kernel_launch(void* const* d_in, const int* in_sizes, int n_in,
                              void* d_out, int out_size)
{
    const float* x      = (const float*)d_in[0];
    const float* w_qkv  = (const float*)d_in[1];
    const float* w_proj = (const float*)d_in[2];
    float* out = (float*)d_out;

    float *qkv, *yb;
    __nv_bfloat16 *xh, *xl, *yh, *yl, *wqh, *wql, *wph, *wpl;
    cudaGetSymbolAddress((void**)&qkv, g_qkv);
    cudaGetSymbolAddress((void**)&yb,  g_y);
    cudaGetSymbolAddress((void**)&xh,  g_xh);
    cudaGetSymbolAddress((void**)&xl,  g_xl);
    cudaGetSymbolAddress((void**)&yh,  g_yh);
    cudaGetSymbolAddress((void**)&yl,  g_yl);
    cudaGetSymbolAddress((void**)&wqh, g_wqh);
    cudaGetSymbolAddress((void**)&wql, g_wql);
    cudaGetSymbolAddress((void**)&wph, g_wph);
    cudaGetSymbolAddress((void**)&wpl, g_wpl);

    cudaFuncSetAttribute(mmasync_kernel, cudaFuncAttributeMaxDynamicSharedMemorySize, MM_SMEM);

    const int n4 = MTOT * CDIM / 4;

    // 1) split X -> bf16 hi/lo
    split_kernel<<<(n4 + 255) / 256, 256>>>(x, xh, xl, n4);

    // 2) transpose+split weights
    {
        dim3 g1(C3 / 32, CDIM / 32), blk(32, 8);
        tsplit_kernel<<<g1, blk>>>(w_qkv, wqh, wql, CDIM, C3);
        dim3 g2(CDIM / 32, CDIM / 32);
        tsplit_kernel<<<g2, blk>>>(w_proj, wph, wpl, CDIM, CDIM);
    }

    // 3) QKV GEMM: (8192 x 3072) = X(8192x1024) @ Wqkv
    {
        dim3 grid(C3 / 128, MTOT / 128);
        mmasync_kernel<<<grid, 256, MM_SMEM>>>(xh, xl, wqh, wql, qkv, C3, CDIM);
    }

    // 4) Flash attention -> g_y
    {
        size_t smem = (3 * 64 * QPAD + 64 * 64) * sizeof(float);
        cudaFuncSetAttribute(flash_kernel, cudaFuncAttributeMaxDynamicSharedMemorySize, (int)smem);
        dim3 grid(TSEQ / 64, NHEAD, BATCH);
        flash_kernel<<<grid, 256, smem>>>(qkv, yb);
    }

    // 5) split Y -> bf16 hi/lo
    split_kernel<<<(n4 + 255) / 256, 256>>>(yb, yh, yl, n4);

    // 6) proj GEMM: (8192 x 1024) = Y @ Wproj
    {
        dim3 grid(CDIM / 128, MTOT / 128);
        mmasync_kernel<<<grid, 256, MM_SMEM>>>(yh, yl, wph, wpl, out, CDIM, CDIM);
    }
    (void)in_sizes; (void)n_in; (void)out_size;
}

// round 4
// speedup vs baseline: 2.5756x; 1.7496x over previous
#include <cuda_runtime.h>
#include <cuda_bf16.h>
#include <cstdint>

// Problem constants
#define BATCH 4
#define TSEQ  2048
#define CDIM  1024
#define NHEAD 16
#define HDIM  64
#define C3    (3*CDIM)
#define MTOT  (BATCH*TSEQ)   // 8192

// fold attention scale * log2(e) into Q so S is directly in exp2 domain
#define QSCALE 0.18033688011112042f   // 0.125 * 1.4426950408889634

// ---------------------------------------------------------------------------
// Device-global scratch (no allocation allowed)
// ---------------------------------------------------------------------------
// QKV split, head-major: [part(0=Q,1=K,2=V)][b][h][t][d]
__device__ __align__(256) __nv_bfloat16 g_qkvh[(size_t)3 * BATCH * NHEAD * TSEQ * HDIM];
__device__ __align__(256) __nv_bfloat16 g_qkvl[(size_t)3 * BATCH * NHEAD * TSEQ * HDIM];
// attention output split: [b][t][C]  (C = h*64+d), K-major for proj GEMM
__device__ __align__(256) __nv_bfloat16 g_yh[(size_t)MTOT * CDIM];
__device__ __align__(256) __nv_bfloat16 g_yl[(size_t)MTOT * CDIM];
// X split
__device__ __align__(256) __nv_bfloat16 g_xh[(size_t)MTOT * CDIM];
__device__ __align__(256) __nv_bfloat16 g_xl[(size_t)MTOT * CDIM];
// transposed weights (N x K)
__device__ __align__(256) __nv_bfloat16 g_wqh[(size_t)C3 * CDIM];
__device__ __align__(256) __nv_bfloat16 g_wql[(size_t)C3 * CDIM];
__device__ __align__(256) __nv_bfloat16 g_wph[(size_t)CDIM * CDIM];
__device__ __align__(256) __nv_bfloat16 g_wpl[(size_t)CDIM * CDIM];

// ---------------------------------------------------------------------------
// Helpers (baseline PTX only)
// ---------------------------------------------------------------------------
__device__ __forceinline__ uint32_t smem_u32(const void* p) {
    uint32_t a;
    asm("{ .reg .u64 t; cvta.to.shared.u64 t, %1; cvt.u32.u64 %0, t; }" : "=r"(a) : "l"(p));
    return a;
}
__device__ __forceinline__ void cpa16(uint32_t dst, const void* src) {
    asm volatile("cp.async.cg.shared.global [%0], [%1], 16;\n" :: "r"(dst), "l"(src));
}
#define CP_COMMIT() asm volatile("cp.async.commit_group;\n" ::: "memory")
#define CP_WAIT(n)  asm volatile("cp.async.wait_group %0;\n" :: "n"(n) : "memory")
#define SWZ128(o) ((o) ^ (((o) >> 3) & 0x70))

__device__ __forceinline__ void ldsm4(uint32_t addr, uint32_t* r) {
    asm volatile("ldmatrix.sync.aligned.m8n8.x4.shared.b16 {%0,%1,%2,%3}, [%4];"
                 : "=r"(r[0]), "=r"(r[1]), "=r"(r[2]), "=r"(r[3]) : "r"(addr));
}
__device__ __forceinline__ void ldsm4t(uint32_t addr, uint32_t* r) {
    asm volatile("ldmatrix.sync.aligned.m8n8.x4.trans.shared.b16 {%0,%1,%2,%3}, [%4];"
                 : "=r"(r[0]), "=r"(r[1]), "=r"(r[2]), "=r"(r[3]) : "r"(addr));
}
__device__ __forceinline__ void mma16816(float* d, const uint32_t* a, uint32_t b0, uint32_t b1) {
    asm volatile("mma.sync.aligned.m16n8k16.row.col.f32.bf16.bf16.f32 "
                 "{%0,%1,%2,%3},{%4,%5,%6,%7},{%8,%9},{%0,%1,%2,%3};"
                 : "+f"(d[0]), "+f"(d[1]), "+f"(d[2]), "+f"(d[3])
                 : "r"(a[0]), "r"(a[1]), "r"(a[2]), "r"(a[3]), "r"(b0), "r"(b1));
}
__device__ __forceinline__ uint32_t packbf2(__nv_bfloat16 a, __nv_bfloat16 b) {
    __nv_bfloat162 t; t.x = a; t.y = b;
    return *reinterpret_cast<uint32_t*>(&t);
}

// ---------------------------------------------------------------------------
// Split fp32 -> bf16 hi/lo (X only)
// ---------------------------------------------------------------------------
__global__ void __launch_bounds__(256) split_kernel(
    const float* __restrict__ in, __nv_bfloat16* __restrict__ hi,
    __nv_bfloat16* __restrict__ lo, int n4)
{
    int i = blockIdx.x * 256 + threadIdx.x;
    if (i >= n4) return;
    float4 v = ((const float4*)in)[i];
    float vv[4] = {v.x, v.y, v.z, v.w};
    __nv_bfloat16 h[4], l[4];
    #pragma unroll
    for (int j = 0; j < 4; j++) {
        h[j] = __float2bfloat16(vv[j]);
        l[j] = __float2bfloat16(vv[j] - __bfloat162float(h[j]));
    }
    ((uint32_t*)hi)[2*i]   = packbf2(h[0], h[1]);
    ((uint32_t*)hi)[2*i+1] = packbf2(h[2], h[3]);
    ((uint32_t*)lo)[2*i]   = packbf2(l[0], l[1]);
    ((uint32_t*)lo)[2*i+1] = packbf2(l[2], l[3]);
}

// ---------------------------------------------------------------------------
// Transpose + split weights: W (KxN fp32, row-major) -> Wt_hi/lo (NxK bf16)
// ---------------------------------------------------------------------------
__global__ void __launch_bounds__(256) tsplit_kernel(
    const float* __restrict__ W, __nv_bfloat16* __restrict__ Th,
    __nv_bfloat16* __restrict__ Tl, int K, int N)
{
    __shared__ float t[32][33];
    int n0 = blockIdx.x * 32, k0 = blockIdx.y * 32;
    int tx = threadIdx.x, ty = threadIdx.y;   // 32 x 8
    #pragma unroll
    for (int i = 0; i < 32; i += 8)
        t[ty + i][tx] = W[(size_t)(k0 + ty + i) * N + n0 + tx];
    __syncthreads();
    #pragma unroll
    for (int i = 0; i < 32; i += 8) {
        float v = t[tx][ty + i];
        __nv_bfloat16 h = __float2bfloat16(v);
        __nv_bfloat16 l = __float2bfloat16(v - __bfloat162float(h));
        size_t o = (size_t)(n0 + ty + i) * K + k0 + tx;
        Th[o] = h; Tl[o] = l;
    }
}

// ---------------------------------------------------------------------------
// mma.sync 3xBF16 GEMM: C(MxN) = A(MxK) * B(NxK)^T
// MODE 0: write fp32 C.  MODE 1: split-write QKV head-major (Q pre-scaled).
// ---------------------------------------------------------------------------
#define TROW_B     80
#define TILE_B     (128 * TROW_B)
#define STAGE_B    (4 * TILE_B)
#define MM_SMEM    (2 * STAGE_B)

template<int MODE>
__global__ void __launch_bounds__(256) mmasync_kernel(
    const __nv_bfloat16* __restrict__ Ah, const __nv_bfloat16* __restrict__ Al,
    const __nv_bfloat16* __restrict__ Bh, const __nv_bfloat16* __restrict__ Bl,
    float* __restrict__ C, int N, int K)
{
    extern __shared__ char smraw[];
    const uint32_t smb = smem_u32(smraw);

    const int tid  = threadIdx.x;
    const int wid  = tid >> 5, lane = tid & 31;
    const int wm   = wid & 1;
    const int wn   = wid >> 1;
    const int bm   = blockIdx.y * 128, bn = blockIdx.x * 128;
    const int l16  = lane & 15, lh = lane >> 4;

    float acc[4][4][4];
    #pragma unroll
    for (int i = 0; i < 4; i++)
        #pragma unroll
        for (int j = 0; j < 4; j++)
            #pragma unroll
            for (int k = 0; k < 4; k++) acc[i][j][k] = 0.f;

    const __nv_bfloat16* srcs[4] = {Ah, Al, Bh, Bl};

    auto fill = [&](int s, int k0) {
        uint32_t sb = smb + (uint32_t)s * STAGE_B;
        #pragma unroll
        for (int t = 0; t < 4; t++) {
            const __nv_bfloat16* src = srcs[t];
            const int rbase = (t < 2) ? bm : bn;
            uint32_t tb = sb + (uint32_t)t * TILE_B;
            #pragma unroll
            for (int i = 0; i < 2; i++) {
                int chunk = tid + i * 256;
                int row = chunk >> 2, c = chunk & 3;
                cpa16(tb + (uint32_t)(row * TROW_B + c * 16),
                      src + (size_t)(rbase + row) * K + k0 + c * 8);
            }
        }
    };

    const int nch = K >> 5;
    fill(0, 0); CP_COMMIT();

    for (int i = 0; i < nch; i++) {
        if (i + 1 < nch) { fill((i + 1) & 1, (i + 1) << 5); CP_COMMIT(); CP_WAIT(1); }
        else             { CP_WAIT(0); }
        __syncthreads();

        uint32_t sb = smb + (uint32_t)(i & 1) * STAGE_B;
        uint32_t Abh = sb, Abl = sb + TILE_B, Bbh = sb + 2 * TILE_B, Bbl = sb + 3 * TILE_B;

        #pragma unroll
        for (int kh = 0; kh < 2; kh++) {
            const uint32_t koff = (uint32_t)(kh * 32 + lh * 16);
            uint32_t ah[4][4], al[4][4];
            #pragma unroll
            for (int mt = 0; mt < 4; mt++) {
                uint32_t ro = (uint32_t)((wm * 64 + mt * 16 + l16) * TROW_B) + koff;
                ldsm4(Abh + ro, ah[mt]);
                ldsm4(Abl + ro, al[mt]);
            }
            uint32_t bh[2][4], bl[2][4];
            #pragma unroll
            for (int np = 0; np < 2; np++) {
                uint32_t ro = (uint32_t)((wn * 32 + np * 16 + l16) * TROW_B) + koff;
                ldsm4(Bbh + ro, bh[np]);
                ldsm4(Bbl + ro, bl[np]);
            }
            #pragma unroll
            for (int mt = 0; mt < 4; mt++)
                #pragma unroll
                for (int nt = 0; nt < 4; nt++) {
                    const int np = nt >> 1, o = nt & 1;
                    mma16816(acc[mt][nt], ah[mt], bh[np][o], bh[np][o + 2]);
                    mma16816(acc[mt][nt], ah[mt], bl[np][o], bl[np][o + 2]);
                    mma16816(acc[mt][nt], al[mt], bh[np][o], bh[np][o + 2]);
                }
        }
        __syncthreads();
    }

    const int er = lane >> 2, ec = (lane & 3) * 2;
    #pragma unroll
    for (int mt = 0; mt < 4; mt++)
        #pragma unroll
        for (int nt = 0; nt < 4; nt++) {
            int r0 = bm + wm * 64 + mt * 16 + er;
            int c0 = bn + wn * 32 + nt * 8 + ec;
            if (MODE == 0) {
                *(float2*)&C[(size_t)r0 * N + c0] =
                    make_float2(acc[mt][nt][0], acc[mt][nt][1]);
                *(float2*)&C[(size_t)(r0 + 8) * N + c0] =
                    make_float2(acc[mt][nt][2], acc[mt][nt][3]);
            } else {
                int bb = r0 >> 11, t = r0 & 2047;
                int part = c0 >> 10, rem = c0 & 1023;
                int hh = rem >> 6, d = rem & 63;
                float sc = (part == 0) ? QSCALE : 1.f;
                size_t o = ((((size_t)part * BATCH + bb) * NHEAD + hh) * TSEQ + t) * HDIM + d;
                #pragma unroll
                for (int rr = 0; rr < 2; rr++) {
                    float v0 = acc[mt][nt][2 * rr + 0] * sc;
                    float v1 = acc[mt][nt][2 * rr + 1] * sc;
                    __nv_bfloat16 h0 = __float2bfloat16(v0);
                    __nv_bfloat16 h1 = __float2bfloat16(v1);
                    __nv_bfloat16 l0 = __float2bfloat16(v0 - __bfloat162float(h0));
                    __nv_bfloat16 l1 = __float2bfloat16(v1 - __bfloat162float(h1));
                    size_t oo = o + (size_t)rr * 8 * HDIM;
                    *(uint32_t*)&g_qkvh[oo] = packbf2(h0, h1);
                    *(uint32_t*)&g_qkvl[oo] = packbf2(l0, l1);
                }
            }
        }
}

// ---------------------------------------------------------------------------
// Tensor-core flash attention (causal), 3x bf16, Bq=128, Bk=64, D=64.
// 256 threads / 8 warps; warp w owns q-rows w*16..w*16+15.
// smem: Qh(16K) Ql(16K) + 2 stages x {Kh,Kl,Vh,Vl} (8K each) = 96KB, SWZ128.
// ---------------------------------------------------------------------------
#define FL_SMEM (96 * 1024)

__global__ void __launch_bounds__(256) flash_tc_kernel()
{
    extern __shared__ char smraw[];
    const uint32_t S = smem_u32(smraw);
    const int tid = threadIdx.x, w = tid >> 5, lane = tid & 31;
    const int l16 = lane & 15, lh = lane >> 4;
    const int b = blockIdx.z, h = blockIdx.y;
    const int qt = (int)(gridDim.x - 1 - blockIdx.x);   // heaviest first
    const int n_kt = 2 * qt + 2;

    const uint32_t Qh_s = S, Ql_s = S + 16384;
    const uint32_t stg0 = S + 32768;    // stage s at stg0 + s*32768

    const size_t head = (((size_t)b) * NHEAD + h) * TSEQ * HDIM;
    const size_t HSZ  = (size_t)BATCH * NHEAD * TSEQ * HDIM;
    const __nv_bfloat16* qh = g_qkvh + head;
    const __nv_bfloat16* ql = g_qkvl + head;
    const __nv_bfloat16* kh = g_qkvh + HSZ + head;
    const __nv_bfloat16* kl = g_qkvl + HSZ + head;
    const __nv_bfloat16* vh = g_qkvh + 2 * HSZ + head;
    const __nv_bfloat16* vl = g_qkvl + 2 * HSZ + head;

    // load Q tiles (2 matrices x 128 rows x 8 chunks = 2048 chunks)
    {
        #pragma unroll
        for (int i = 0; i < 8; i++) {
            int idx = tid + i * 256;
            int mtx = idx >> 10, row = (idx >> 3) & 127, c = idx & 7;
            const __nv_bfloat16* src = (mtx ? ql : qh) + (size_t)(qt * 128 + row) * HDIM + c * 8;
            cpa16((mtx ? Ql_s : Qh_s) + SWZ128((uint32_t)(row * 128 + c * 16)), src);
        }
    }
    // fill K/V stage
    auto fillkv = [&](int s, int kt) {
        uint32_t sb = stg0 + (uint32_t)s * 32768u;
        const __nv_bfloat16* bases[4] = {kh, kl, vh, vl};
        #pragma unroll
        for (int i = 0; i < 8; i++) {
            int idx = tid + i * 256;
            int mtx = idx >> 9, row = (idx >> 3) & 63, c = idx & 7;
            cpa16(sb + (uint32_t)mtx * 8192u + SWZ128((uint32_t)(row * 128 + c * 16)),
                  bases[mtx] + (size_t)(kt * 64 + row) * HDIM + c * 8);
        }
    };

    fillkv(0, 0); CP_COMMIT();
    if (n_kt > 1) { fillkv(1, 1); CP_COMMIT(); }

    float m0 = -1e30f, m1 = -1e30f, l0 = 0.f, l1 = 0.f;
    float o[8][4];
    #pragma unroll
    for (int j = 0; j < 8; j++)
        #pragma unroll
        for (int e = 0; e < 4; e++) o[j][e] = 0.f;

    for (int kt = 0; kt < n_kt; kt++) {
        if (kt + 1 < n_kt) { CP_WAIT(1); } else { CP_WAIT(0); }
        __syncthreads();

        const uint32_t sb   = stg0 + (uint32_t)(kt & 1) * 32768u;
        const uint32_t Kh_s = sb, Kl_s = sb + 8192, Vh_s = sb + 16384, Vl_s = sb + 24576;

        // ---- S = Q K^T (3-term) ----
        float s[8][4];
        #pragma unroll
        for (int j = 0; j < 8; j++)
            #pragma unroll
            for (int e = 0; e < 4; e++) s[j][e] = 0.f;

        #pragma unroll
        for (int kk = 0; kk < 4; kk++) {
            const uint32_t koff = (uint32_t)(kk * 32 + lh * 16);
            uint32_t qf[4], qlf[4];
            ldsm4(Qh_s + SWZ128((uint32_t)((w * 16 + l16) * 128) + koff), qf);
            ldsm4(Ql_s + SWZ128((uint32_t)((w * 16 + l16) * 128) + koff), qlf);
            #pragma unroll
            for (int g = 0; g < 4; g++) {
                uint32_t kf[4], klf[4];
                uint32_t ro = SWZ128((uint32_t)((g * 16 + l16) * 128) + koff);
                ldsm4(Kh_s + ro, kf);
                ldsm4(Kl_s + ro, klf);
                mma16816(s[2 * g],     qf,  kf[0],  kf[2]);
                mma16816(s[2 * g],     qf,  klf[0], klf[2]);
                mma16816(s[2 * g],     qlf, kf[0],  kf[2]);
                mma16816(s[2 * g + 1], qf,  kf[1],  kf[3]);
                mma16816(s[2 * g + 1], qf,  klf[1], klf[3]);
                mma16816(s[2 * g + 1], qlf, kf[1],  kf[3]);
            }
        }

        // ---- causal mask ----
        const int row0 = qt * 128 + w * 16 + (lane >> 2);
        if (kt * 64 + 63 > qt * 128 + w * 16) {
            #pragma unroll
            for (int j = 0; j < 8; j++) {
                int colb = kt * 64 + j * 8 + (lane & 3) * 2;
                if (colb + 0 > row0)     s[j][0] = -1e30f;
                if (colb + 1 > row0)     s[j][1] = -1e30f;
                if (colb + 0 > row0 + 8) s[j][2] = -1e30f;
                if (colb + 1 > row0 + 8) s[j][3] = -1e30f;
            }
        }

        // ---- online softmax (exp2 domain; scale folded into Q) ----
        float mx0 = -1e30f, mx1 = -1e30f;
        #pragma unroll
        for (int j = 0; j < 8; j++) {
            mx0 = fmaxf(mx0, fmaxf(s[j][0], s[j][1]));
            mx1 = fmaxf(mx1, fmaxf(s[j][2], s[j][3]));
        }
        mx0 = fmaxf(mx0, __shfl_xor_sync(0xffffffffu, mx0, 1));
        mx0 = fmaxf(mx0, __shfl_xor_sync(0xffffffffu, mx0, 2));
        mx1 = fmaxf(mx1, __shfl_xor_sync(0xffffffffu, mx1, 1));
        mx1 = fmaxf(mx1, __shfl_xor_sync(0xffffffffu, mx1, 2));
        float nm0 = fmaxf(m0, mx0), nm1 = fmaxf(m1, mx1);
        float c0 = exp2f(m0 - nm0), c1 = exp2f(m1 - nm1);
        m0 = nm0; m1 = nm1;
        float sum0 = 0.f, sum1 = 0.f;
        #pragma unroll
        for (int j = 0; j < 8; j++) {
            s[j][0] = exp2f(s[j][0] - m0);
            s[j][1] = exp2f(s[j][1] - m0);
            s[j][2] = exp2f(s[j][2] - m1);
            s[j][3] = exp2f(s[j][3] - m1);
            sum0 += s[j][0] + s[j][1];
            sum1 += s[j][2] + s[j][3];
        }
        sum0 += __shfl_xor_sync(0xffffffffu, sum0, 1);
        sum0 += __shfl_xor_sync(0xffffffffu, sum0, 2);
        sum1 += __shfl_xor_sync(0xffffffffu, sum1, 1);
        sum1 += __shfl_xor_sync(0xffffffffu, sum1, 2);
        l0 = l0 * c0 + sum0;
        l1 = l1 * c1 + sum1;
        #pragma unroll
        for (int j = 0; j < 8; j++) {
            o[j][0] *= c0; o[j][1] *= c0; o[j][2] *= c1; o[j][3] *= c1;
        }

        // ---- O += P V (3-term, P in registers) ----
        #pragma unroll
        for (int kk = 0; kk < 4; kk++) {
            uint32_t ph[4], pl[4];
            #pragma unroll
            for (int half = 0; half < 2; half++) {
                const int f = 2 * kk + half;
                __nv_bfloat16 h0 = __float2bfloat16(s[f][0]);
                __nv_bfloat16 h1 = __float2bfloat16(s[f][1]);
                __nv_bfloat16 h2 = __float2bfloat16(s[f][2]);
                __nv_bfloat16 h3 = __float2bfloat16(s[f][3]);
                ph[2 * half + 0] = packbf2(h0, h1);
                ph[2 * half + 1] = packbf2(h2, h3);
                pl[2 * half + 0] = packbf2(
                    __float2bfloat16(s[f][0] - __bfloat162float(h0)),
                    __float2bfloat16(s[f][1] - __bfloat162float(h1)));
                pl[2 * half + 1] = packbf2(
                    __float2bfloat16(s[f][2] - __bfloat162float(h2)),
                    __float2bfloat16(s[f][3] - __bfloat162float(h3)));
            }
            // A-frag order: a0=(r,klo) a1=(r+8,klo) a2=(r,khi) a3=(r+8,khi)
            uint32_t pa[4] = {ph[0], ph[1], ph[2], ph[3]};
            uint32_t pb[4] = {pl[0], pl[1], pl[2], pl[3]};
            #pragma unroll
            for (int g = 0; g < 4; g++) {
                uint32_t vf[4], vlf[4];
                uint32_t ro = SWZ128((uint32_t)((kk * 16 + l16) * 128 + g * 32) + (uint32_t)(lh * 16));
                ldsm4t(Vh_s + ro, vf);
                ldsm4t(Vl_s + ro, vlf);
                mma16816(o[2 * g],     pa, vf[0],  vf[1]);
                mma16816(o[2 * g],     pa, vlf[0], vlf[1]);
                mma16816(o[2 * g],     pb, vf[0],  vf[1]);
                mma16816(o[2 * g + 1], pa, vf[2],  vf[3]);
                mma16816(o[2 * g + 1], pa, vlf[2], vlf[3]);
                mma16816(o[2 * g + 1], pb, vf[2],  vf[3]);
            }
        }

        __syncthreads();
        if (kt + 2 < n_kt) { fillkv(kt & 1, kt + 2); CP_COMMIT(); }
    }

    // ---- epilogue: normalize, split to bf16 hi/lo, write y ----
    const float inv0 = 1.f / l0, inv1 = 1.f / l1;
    const int r0 = qt * 128 + w * 16 + (lane >> 2);
    const int t0 = r0, t1 = r0 + 8;
    #pragma unroll
    for (int j = 0; j < 8; j++) {
        int d = j * 8 + (lane & 3) * 2;
        size_t o0 = ((size_t)b * TSEQ + t0) * CDIM + h * HDIM + d;
        size_t o1 = ((size_t)b * TSEQ + t1) * CDIM + h * HDIM + d;
        float y0 = o[j][0] * inv0, y1 = o[j][1] * inv0;
        float y2 = o[j][2] * inv1, y3 = o[j][3] * inv1;
        __nv_bfloat16 h0 = __float2bfloat16(y0), h1 = __float2bfloat16(y1);
        __nv_bfloat16 h2 = __float2bfloat16(y2), h3 = __float2bfloat16(y3);
        *(uint32_t*)&g_yh[o0] = packbf2(h0, h1);
        *(uint32_t*)&g_yh[o1] = packbf2(h2, h3);
        *(uint32_t*)&g_yl[o0] = packbf2(
            __float2bfloat16(y0 - __bfloat162float(h0)),
            __float2bfloat16(y1 - __bfloat162float(h1)));
        *(uint32_t*)&g_yl[o1] = packbf2(
            __float2bfloat16(y2 - __bfloat162float(h2)),
            __float2bfloat16(y3 - __bfloat162float(h3)));
    }
}

// ---------------------------------------------------------------------------
extern "C" void kernel_launch(void* const* d_in, const int* in_sizes, int n_in,
                              void* d_out, int out_size)
{
    const float* x      = (const float*)d_in[0];
    const float* w_qkv  = (const float*)d_in[1];
    const float* w_proj = (const float*)d_in[2];
    float* out = (float*)d_out;

    __nv_bfloat16 *xh, *xl, *yh, *yl, *wqh, *wql, *wph, *wpl;
    cudaGetSymbolAddress((void**)&xh,  g_xh);
    cudaGetSymbolAddress((void**)&xl,  g_xl);
    cudaGetSymbolAddress((void**)&yh,  g_yh);
    cudaGetSymbolAddress((void**)&yl,  g_yl);
    cudaGetSymbolAddress((void**)&wqh, g_wqh);
    cudaGetSymbolAddress((void**)&wql, g_wql);
    cudaGetSymbolAddress((void**)&wph, g_wph);
    cudaGetSymbolAddress((void**)&wpl, g_wpl);

    cudaFuncSetAttribute(mmasync_kernel<0>, cudaFuncAttributeMaxDynamicSharedMemorySize, MM_SMEM);
    cudaFuncSetAttribute(mmasync_kernel<1>, cudaFuncAttributeMaxDynamicSharedMemorySize, MM_SMEM);
    cudaFuncSetAttribute(flash_tc_kernel,   cudaFuncAttributeMaxDynamicSharedMemorySize, FL_SMEM);

    const int n4 = MTOT * CDIM / 4;

    // 1) split X -> bf16 hi/lo
    split_kernel<<<(n4 + 255) / 256, 256>>>(x, xh, xl, n4);

    // 2) transpose+split weights
    {
        dim3 g1(C3 / 32, CDIM / 32), blk(32, 8);
        tsplit_kernel<<<g1, blk>>>(w_qkv, wqh, wql, CDIM, C3);
        dim3 g2(CDIM / 32, CDIM / 32);
        tsplit_kernel<<<g2, blk>>>(w_proj, wph, wpl, CDIM, CDIM);
    }

    // 3) QKV GEMM with split/head-major epilogue (Q pre-scaled)
    {
        dim3 grid(C3 / 128, MTOT / 128);
        mmasync_kernel<1><<<grid, 256, MM_SMEM>>>(xh, xl, wqh, wql, nullptr, C3, CDIM);
    }

    // 4) tensor-core flash attention -> g_yh/g_yl
    {
        dim3 grid(TSEQ / 128, NHEAD, BATCH);
        flash_tc_kernel<<<grid, 256, FL_SMEM>>>();
    }

    // 5) proj GEMM: out = Y @ Wproj (fp32 epilogue)
    {
        dim3 grid(CDIM / 128, MTOT / 128);
        mmasync_kernel<0><<<grid, 256, MM_SMEM>>>(yh, yl, wph, wpl, out, CDIM, CDIM);
    }
    (void)in_sizes; (void)n_in; (void)out_size;
}

// round 5
// speedup vs baseline: 2.7408x; 1.0641x over previous
#include <cuda_runtime.h>
#include <cuda_bf16.h>
#include <cstdint>

// Problem constants
#define BATCH 4
#define TSEQ  2048
#define CDIM  1024
#define NHEAD 16
#define HDIM  64
#define C3    (3*CDIM)
#define MTOT  (BATCH*TSEQ)   // 8192

// fold attention scale * log2(e) into Q so S is directly in exp2 domain
#define QSCALE 0.18033688011112042f   // 0.125 * 1.4426950408889634

// ---------------------------------------------------------------------------
// Device-global scratch (no allocation allowed)
// ---------------------------------------------------------------------------
__device__ __align__(256) __nv_bfloat16 g_qkvh[(size_t)3 * BATCH * NHEAD * TSEQ * HDIM];
__device__ __align__(256) __nv_bfloat16 g_qkvl[(size_t)3 * BATCH * NHEAD * TSEQ * HDIM];
__device__ __align__(256) __nv_bfloat16 g_yh[(size_t)MTOT * CDIM];
__device__ __align__(256) __nv_bfloat16 g_yl[(size_t)MTOT * CDIM];
__device__ __align__(256) __nv_bfloat16 g_xh[(size_t)MTOT * CDIM];
__device__ __align__(256) __nv_bfloat16 g_xl[(size_t)MTOT * CDIM];
__device__ __align__(256) __nv_bfloat16 g_wqh[(size_t)C3 * CDIM];
__device__ __align__(256) __nv_bfloat16 g_wql[(size_t)C3 * CDIM];
__device__ __align__(256) __nv_bfloat16 g_wph[(size_t)CDIM * CDIM];
__device__ __align__(256) __nv_bfloat16 g_wpl[(size_t)CDIM * CDIM];

// ---------------------------------------------------------------------------
// Helpers (baseline PTX only)
// ---------------------------------------------------------------------------
__device__ __forceinline__ uint32_t smem_u32(const void* p) {
    uint32_t a;
    asm("{ .reg .u64 t; cvta.to.shared.u64 t, %1; cvt.u32.u64 %0, t; }" : "=r"(a) : "l"(p));
    return a;
}
__device__ __forceinline__ void cpa16(uint32_t dst, const void* src) {
    asm volatile("cp.async.cg.shared.global [%0], [%1], 16;\n" :: "r"(dst), "l"(src));
}
#define CP_COMMIT() asm volatile("cp.async.commit_group;\n" ::: "memory")
#define CP_WAIT(n)  asm volatile("cp.async.wait_group %0;\n" :: "n"(n) : "memory")
#define SWZ128(o) ((o) ^ (((o) >> 3) & 0x70))
#define SWZ64(o)  ((o) ^ (((o) >> 3) & 0x30))

__device__ __forceinline__ void ldsm4(uint32_t addr, uint32_t* r) {
    asm volatile("ldmatrix.sync.aligned.m8n8.x4.shared.b16 {%0,%1,%2,%3}, [%4];"
                 : "=r"(r[0]), "=r"(r[1]), "=r"(r[2]), "=r"(r[3]) : "r"(addr));
}
__device__ __forceinline__ void ldsm4t(uint32_t addr, uint32_t* r) {
    asm volatile("ldmatrix.sync.aligned.m8n8.x4.trans.shared.b16 {%0,%1,%2,%3}, [%4];"
                 : "=r"(r[0]), "=r"(r[1]), "=r"(r[2]), "=r"(r[3]) : "r"(addr));
}
__device__ __forceinline__ void mma16816(float* d, const uint32_t* a, uint32_t b0, uint32_t b1) {
    asm volatile("mma.sync.aligned.m16n8k16.row.col.f32.bf16.bf16.f32 "
                 "{%0,%1,%2,%3},{%4,%5,%6,%7},{%8,%9},{%0,%1,%2,%3};"
                 : "+f"(d[0]), "+f"(d[1]), "+f"(d[2]), "+f"(d[3])
                 : "r"(a[0]), "r"(a[1]), "r"(a[2]), "r"(a[3]), "r"(b0), "r"(b1));
}
__device__ __forceinline__ uint32_t packbf2(__nv_bfloat16 a, __nv_bfloat16 b) {
    __nv_bfloat162 t; t.x = a; t.y = b;
    return *reinterpret_cast<uint32_t*>(&t);
}

// ---------------------------------------------------------------------------
// Split fp32 -> bf16 hi/lo
// ---------------------------------------------------------------------------
__global__ void __launch_bounds__(256) split_kernel(
    const float* __restrict__ in, __nv_bfloat16* __restrict__ hi,
    __nv_bfloat16* __restrict__ lo, int n4)
{
    int i = blockIdx.x * 256 + threadIdx.x;
    if (i >= n4) return;
    float4 v = ((const float4*)in)[i];
    float vv[4] = {v.x, v.y, v.z, v.w};
    __nv_bfloat16 h[4], l[4];
    #pragma unroll
    for (int j = 0; j < 4; j++) {
        h[j] = __float2bfloat16(vv[j]);
        l[j] = __float2bfloat16(vv[j] - __bfloat162float(h[j]));
    }
    ((uint32_t*)hi)[2*i]   = packbf2(h[0], h[1]);
    ((uint32_t*)hi)[2*i+1] = packbf2(h[2], h[3]);
    ((uint32_t*)lo)[2*i]   = packbf2(l[0], l[1]);
    ((uint32_t*)lo)[2*i+1] = packbf2(l[2], l[3]);
}

// ---------------------------------------------------------------------------
// Transpose + split weights
// ---------------------------------------------------------------------------
__global__ void __launch_bounds__(256) tsplit_kernel(
    const float* __restrict__ W, __nv_bfloat16* __restrict__ Th,
    __nv_bfloat16* __restrict__ Tl, int K, int N)
{
    __shared__ float t[32][33];
    int n0 = blockIdx.x * 32, k0 = blockIdx.y * 32;
    int tx = threadIdx.x, ty = threadIdx.y;
    #pragma unroll
    for (int i = 0; i < 32; i += 8)
        t[ty + i][tx] = W[(size_t)(k0 + ty + i) * N + n0 + tx];
    __syncthreads();
    #pragma unroll
    for (int i = 0; i < 32; i += 8) {
        float v = t[tx][ty + i];
        __nv_bfloat16 h = __float2bfloat16(v);
        __nv_bfloat16 l = __float2bfloat16(v - __bfloat162float(h));
        size_t o = (size_t)(n0 + ty + i) * K + k0 + tx;
        Th[o] = h; Tl[o] = l;
    }
}

// ---------------------------------------------------------------------------
// mma.sync 3xBF16 GEMM: C(MxN) = A(MxK) * B(NxK)^T
// SW64 layout: 64B rows (BK=32 bf16), tile 8KB; 2 stages x 4 tiles = 64KB.
// MODE 0: fp32 C.  MODE 1: split-write QKV head-major (Q pre-scaled).
// ---------------------------------------------------------------------------
#define TILE_B     (128 * 64)            // 8192 B per tile
#define STAGE_B    (4 * TILE_B)          // 32768 B
#define MM_SMEM    (2 * STAGE_B)         // 65536 B

template<int MODE>
__global__ void __launch_bounds__(256, 2) mmasync_kernel(
    const __nv_bfloat16* __restrict__ Ah, const __nv_bfloat16* __restrict__ Al,
    const __nv_bfloat16* __restrict__ Bh, const __nv_bfloat16* __restrict__ Bl,
    float* __restrict__ C, int N, int K)
{
    extern __shared__ char smraw[];
    const uint32_t smb = smem_u32(smraw);

    const int tid  = threadIdx.x;
    const int wid  = tid >> 5, lane = tid & 31;
    const int wm   = wid & 1;
    const int wn   = wid >> 1;
    const int bm   = blockIdx.y * 128, bn = blockIdx.x * 128;
    const int l16  = lane & 15, lh = lane >> 4;

    float acc[4][4][4];
    #pragma unroll
    for (int i = 0; i < 4; i++)
        #pragma unroll
        for (int j = 0; j < 4; j++)
            #pragma unroll
            for (int k = 0; k < 4; k++) acc[i][j][k] = 0.f;

    const __nv_bfloat16* srcs[4] = {Ah, Al, Bh, Bl};

    // fill one stage: 4 tiles x 128 rows x 4 chunks(16B) = 2048 chunks, 8/thread
    auto fill = [&](int s, int k0) {
        uint32_t sb = smb + (uint32_t)s * STAGE_B;
        #pragma unroll
        for (int t = 0; t < 4; t++) {
            const __nv_bfloat16* src = srcs[t];
            const int rbase = (t < 2) ? bm : bn;
            uint32_t tb = sb + (uint32_t)t * TILE_B;
            #pragma unroll
            for (int i = 0; i < 2; i++) {
                int chunk = tid + i * 256;       // 0..511
                int row = chunk >> 2, c = chunk & 3;
                cpa16(tb + SWZ64((uint32_t)(row * 64 + c * 16)),
                      src + (size_t)(rbase + row) * K + k0 + c * 8);
            }
        }
    };

    const int nch = K >> 5;   // BK = 32
    fill(0, 0); CP_COMMIT();

    for (int i = 0; i < nch; i++) {
        if (i + 1 < nch) { fill((i + 1) & 1, (i + 1) << 5); CP_COMMIT(); CP_WAIT(1); }
        else             { CP_WAIT(0); }
        __syncthreads();

        uint32_t sb = smb + (uint32_t)(i & 1) * STAGE_B;
        uint32_t Abh = sb, Abl = sb + TILE_B, Bbh = sb + 2 * TILE_B, Bbl = sb + 3 * TILE_B;

        #pragma unroll
        for (int kh = 0; kh < 2; kh++) {
            const uint32_t koff = (uint32_t)(kh * 32 + lh * 16);
            uint32_t ah[4][4], al[4][4];
            #pragma unroll
            for (int mt = 0; mt < 4; mt++) {
                uint32_t ro = SWZ64((uint32_t)((wm * 64 + mt * 16 + l16) * 64) + koff);
                ldsm4(Abh + ro, ah[mt]);
                ldsm4(Abl + ro, al[mt]);
            }
            uint32_t bh[2][4], bl[2][4];
            #pragma unroll
            for (int np = 0; np < 2; np++) {
                uint32_t ro = SWZ64((uint32_t)((wn * 32 + np * 16 + l16) * 64) + koff);
                ldsm4(Bbh + ro, bh[np]);
                ldsm4(Bbl + ro, bl[np]);
            }
            #pragma unroll
            for (int mt = 0; mt < 4; mt++)
                #pragma unroll
                for (int nt = 0; nt < 4; nt++) {
                    const int np = nt >> 1, o = nt & 1;
                    mma16816(acc[mt][nt], ah[mt], bh[np][o], bh[np][o + 2]);
                    mma16816(acc[mt][nt], ah[mt], bl[np][o], bl[np][o + 2]);
                    mma16816(acc[mt][nt], al[mt], bh[np][o], bh[np][o + 2]);
                }
        }
        __syncthreads();
    }

    const int er = lane >> 2, ec = (lane & 3) * 2;
    #pragma unroll
    for (int mt = 0; mt < 4; mt++)
        #pragma unroll
        for (int nt = 0; nt < 4; nt++) {
            int r0 = bm + wm * 64 + mt * 16 + er;
            int c0 = bn + wn * 32 + nt * 8 + ec;
            if (MODE == 0) {
                *(float2*)&C[(size_t)r0 * N + c0] =
                    make_float2(acc[mt][nt][0], acc[mt][nt][1]);
                *(float2*)&C[(size_t)(r0 + 8) * N + c0] =
                    make_float2(acc[mt][nt][2], acc[mt][nt][3]);
            } else {
                int bb = r0 >> 11, t = r0 & 2047;
                int part = c0 >> 10, rem = c0 & 1023;
                int hh = rem >> 6, d = rem & 63;
                float sc = (part == 0) ? QSCALE : 1.f;
                size_t o = ((((size_t)part * BATCH + bb) * NHEAD + hh) * TSEQ + t) * HDIM + d;
                #pragma unroll
                for (int rr = 0; rr < 2; rr++) {
                    float v0 = acc[mt][nt][2 * rr + 0] * sc;
                    float v1 = acc[mt][nt][2 * rr + 1] * sc;
                    __nv_bfloat16 h0 = __float2bfloat16(v0);
                    __nv_bfloat16 h1 = __float2bfloat16(v1);
                    __nv_bfloat16 l0 = __float2bfloat16(v0 - __bfloat162float(h0));
                    __nv_bfloat16 l1 = __float2bfloat16(v1 - __bfloat162float(h1));
                    size_t oo = o + (size_t)rr * 8 * HDIM;
                    *(uint32_t*)&g_qkvh[oo] = packbf2(h0, h1);
                    *(uint32_t*)&g_qkvl[oo] = packbf2(l0, l1);
                }
            }
        }
}

// ---------------------------------------------------------------------------
// Tensor-core flash attention (causal), 3x bf16, Bq=128, Bk=64, D=64.
// ---------------------------------------------------------------------------
#define FL_SMEM (96 * 1024)

__global__ void __launch_bounds__(256, 2) flash_tc_kernel()
{
    extern __shared__ char smraw[];
    const uint32_t S = smem_u32(smraw);
    const int tid = threadIdx.x, w = tid >> 5, lane = tid & 31;
    const int l16 = lane & 15, lh = lane >> 4;
    const int b = blockIdx.z, h = blockIdx.y;
    const int qt = (int)(gridDim.x - 1 - blockIdx.x);   // heaviest first
    const int n_kt = 2 * qt + 2;

    const uint32_t Qh_s = S, Ql_s = S + 16384;
    const uint32_t stg0 = S + 32768;

    const size_t head = (((size_t)b) * NHEAD + h) * TSEQ * HDIM;
    const size_t HSZ  = (size_t)BATCH * NHEAD * TSEQ * HDIM;
    const __nv_bfloat16* qh = g_qkvh + head;
    const __nv_bfloat16* ql = g_qkvl + head;
    const __nv_bfloat16* kh = g_qkvh + HSZ + head;
    const __nv_bfloat16* kl = g_qkvl + HSZ + head;
    const __nv_bfloat16* vh = g_qkvh + 2 * HSZ + head;
    const __nv_bfloat16* vl = g_qkvl + 2 * HSZ + head;

    {
        #pragma unroll
        for (int i = 0; i < 8; i++) {
            int idx = tid + i * 256;
            int mtx = idx >> 10, row = (idx >> 3) & 127, c = idx & 7;
            const __nv_bfloat16* src = (mtx ? ql : qh) + (size_t)(qt * 128 + row) * HDIM + c * 8;
            cpa16((mtx ? Ql_s : Qh_s) + SWZ128((uint32_t)(row * 128 + c * 16)), src);
        }
    }
    auto fillkv = [&](int s, int kt) {
        uint32_t sb = stg0 + (uint32_t)s * 32768u;
        const __nv_bfloat16* bases[4] = {kh, kl, vh, vl};
        #pragma unroll
        for (int i = 0; i < 8; i++) {
            int idx = tid + i * 256;
            int mtx = idx >> 9, row = (idx >> 3) & 63, c = idx & 7;
            cpa16(sb + (uint32_t)mtx * 8192u + SWZ128((uint32_t)(row * 128 + c * 16)),
                  bases[mtx] + (size_t)(kt * 64 + row) * HDIM + c * 8);
        }
    };

    fillkv(0, 0); CP_COMMIT();
    if (n_kt > 1) { fillkv(1, 1); CP_COMMIT(); }

    float m0 = -1e30f, m1 = -1e30f, l0 = 0.f, l1 = 0.f;
    float o[8][4];
    #pragma unroll
    for (int j = 0; j < 8; j++)
        #pragma unroll
        for (int e = 0; e < 4; e++) o[j][e] = 0.f;

    for (int kt = 0; kt < n_kt; kt++) {
        if (kt + 1 < n_kt) { CP_WAIT(1); } else { CP_WAIT(0); }
        __syncthreads();

        const uint32_t sb   = stg0 + (uint32_t)(kt & 1) * 32768u;
        const uint32_t Kh_s = sb, Kl_s = sb + 8192, Vh_s = sb + 16384, Vl_s = sb + 24576;

        float s[8][4];
        #pragma unroll
        for (int j = 0; j < 8; j++)
            #pragma unroll
            for (int e = 0; e < 4; e++) s[j][e] = 0.f;

        #pragma unroll
        for (int kk = 0; kk < 4; kk++) {
            const uint32_t koff = (uint32_t)(kk * 32 + lh * 16);
            uint32_t qf[4], qlf[4];
            ldsm4(Qh_s + SWZ128((uint32_t)((w * 16 + l16) * 128) + koff), qf);
            ldsm4(Ql_s + SWZ128((uint32_t)((w * 16 + l16) * 128) + koff), qlf);
            #pragma unroll
            for (int g = 0; g < 4; g++) {
                uint32_t kf[4], klf[4];
                uint32_t ro = SWZ128((uint32_t)((g * 16 + l16) * 128) + koff);
                ldsm4(Kh_s + ro, kf);
                ldsm4(Kl_s + ro, klf);
                mma16816(s[2 * g],     qf,  kf[0],  kf[2]);
                mma16816(s[2 * g],     qf,  klf[0], klf[2]);
                mma16816(s[2 * g],     qlf, kf[0],  kf[2]);
                mma16816(s[2 * g + 1], qf,  kf[1],  kf[3]);
                mma16816(s[2 * g + 1], qf,  klf[1], klf[3]);
                mma16816(s[2 * g + 1], qlf, kf[1],  kf[3]);
            }
        }

        const int row0 = qt * 128 + w * 16 + (lane >> 2);
        if (kt * 64 + 63 > qt * 128 + w * 16) {
            #pragma unroll
            for (int j = 0; j < 8; j++) {
                int colb = kt * 64 + j * 8 + (lane & 3) * 2;
                if (colb + 0 > row0)     s[j][0] = -1e30f;
                if (colb + 1 > row0)     s[j][1] = -1e30f;
                if (colb + 0 > row0 + 8) s[j][2] = -1e30f;
                if (colb + 1 > row0 + 8) s[j][3] = -1e30f;
            }
        }

        float mx0 = -1e30f, mx1 = -1e30f;
        #pragma unroll
        for (int j = 0; j < 8; j++) {
            mx0 = fmaxf(mx0, fmaxf(s[j][0], s[j][1]));
            mx1 = fmaxf(mx1, fmaxf(s[j][2], s[j][3]));
        }
        mx0 = fmaxf(mx0, __shfl_xor_sync(0xffffffffu, mx0, 1));
        mx0 = fmaxf(mx0, __shfl_xor_sync(0xffffffffu, mx0, 2));
        mx1 = fmaxf(mx1, __shfl_xor_sync(0xffffffffu, mx1, 1));
        mx1 = fmaxf(mx1, __shfl_xor_sync(0xffffffffu, mx1, 2));
        float nm0 = fmaxf(m0, mx0), nm1 = fmaxf(m1, mx1);
        float c0 = exp2f(m0 - nm0), c1 = exp2f(m1 - nm1);
        m0 = nm0; m1 = nm1;
        float sum0 = 0.f, sum1 = 0.f;
        #pragma unroll
        for (int j = 0; j < 8; j++) {
            s[j][0] = exp2f(s[j][0] - m0);
            s[j][1] = exp2f(s[j][1] - m0);
            s[j][2] = exp2f(s[j][2] - m1);
            s[j][3] = exp2f(s[j][3] - m1);
            sum0 += s[j][0] + s[j][1];
            sum1 += s[j][2] + s[j][3];
        }
        sum0 += __shfl_xor_sync(0xffffffffu, sum0, 1);
        sum0 += __shfl_xor_sync(0xffffffffu, sum0, 2);
        sum1 += __shfl_xor_sync(0xffffffffu, sum1, 1);
        sum1 += __shfl_xor_sync(0xffffffffu, sum1, 2);
        l0 = l0 * c0 + sum0;
        l1 = l1 * c1 + sum1;
        #pragma unroll
        for (int j = 0; j < 8; j++) {
            o[j][0] *= c0; o[j][1] *= c0; o[j][2] *= c1; o[j][3] *= c1;
        }

        #pragma unroll
        for (int kk = 0; kk < 4; kk++) {
            uint32_t ph[4], pl[4];
            #pragma unroll
            for (int half = 0; half < 2; half++) {
                const int f = 2 * kk + half;
                __nv_bfloat16 h0 = __float2bfloat16(s[f][0]);
                __nv_bfloat16 h1 = __float2bfloat16(s[f][1]);
                __nv_bfloat16 h2 = __float2bfloat16(s[f][2]);
                __nv_bfloat16 h3 = __float2bfloat16(s[f][3]);
                ph[2 * half + 0] = packbf2(h0, h1);
                ph[2 * half + 1] = packbf2(h2, h3);
                pl[2 * half + 0] = packbf2(
                    __float2bfloat16(s[f][0] - __bfloat162float(h0)),
                    __float2bfloat16(s[f][1] - __bfloat162float(h1)));
                pl[2 * half + 1] = packbf2(
                    __float2bfloat16(s[f][2] - __bfloat162float(h2)),
                    __float2bfloat16(s[f][3] - __bfloat162float(h3)));
            }
            uint32_t pa[4] = {ph[0], ph[1], ph[2], ph[3]};
            uint32_t pb[4] = {pl[0], pl[1], pl[2], pl[3]};
            #pragma unroll
            for (int g = 0; g < 4; g++) {
                uint32_t vf[4], vlf[4];
                uint32_t ro = SWZ128((uint32_t)((kk * 16 + l16) * 128 + g * 32) + (uint32_t)(lh * 16));
                ldsm4t(Vh_s + ro, vf);
                ldsm4t(Vl_s + ro, vlf);
                mma16816(o[2 * g],     pa, vf[0],  vf[1]);
                mma16816(o[2 * g],     pa, vlf[0], vlf[1]);
                mma16816(o[2 * g],     pb, vf[0],  vf[1]);
                mma16816(o[2 * g + 1], pa, vf[2],  vf[3]);
                mma16816(o[2 * g + 1], pa, vlf[2], vlf[3]);
                mma16816(o[2 * g + 1], pb, vf[2],  vf[3]);
            }
        }

        __syncthreads();
        if (kt + 2 < n_kt) { fillkv(kt & 1, kt + 2); CP_COMMIT(); }
    }

    const float inv0 = 1.f / l0, inv1 = 1.f / l1;
    const int r0 = qt * 128 + w * 16 + (lane >> 2);
    const int t0 = r0, t1 = r0 + 8;
    #pragma unroll
    for (int j = 0; j < 8; j++) {
        int d = j * 8 + (lane & 3) * 2;
        size_t o0 = ((size_t)b * TSEQ + t0) * CDIM + h * HDIM + d;
        size_t o1 = ((size_t)b * TSEQ + t1) * CDIM + h * HDIM + d;
        float y0 = o[j][0] * inv0, y1 = o[j][1] * inv0;
        float y2 = o[j][2] * inv1, y3 = o[j][3] * inv1;
        __nv_bfloat16 h0 = __float2bfloat16(y0), h1 = __float2bfloat16(y1);
        __nv_bfloat16 h2 = __float2bfloat16(y2), h3 = __float2bfloat16(y3);
        *(uint32_t*)&g_yh[o0] = packbf2(h0, h1);
        *(uint32_t*)&g_yh[o1] = packbf2(h2, h3);
        *(uint32_t*)&g_yl[o0] = packbf2(
            __float2bfloat16(y0 - __bfloat162float(h0)),
            __float2bfloat16(y1 - __bfloat162float(h1)));
        *(uint32_t*)&g_yl[o1] = packbf2(
            __float2bfloat16(y2 - __bfloat162float(h2)),
            __float2bfloat16(y3 - __bfloat162float(h3)));
    }
}

// ---------------------------------------------------------------------------
extern "C" void kernel_launch(void* const* d_in, const int* in_sizes, int n_in,
                              void* d_out, int out_size)
{
    const float* x      = (const float*)d_in[0];
    const float* w_qkv  = (const float*)d_in[1];
    const float* w_proj = (const float*)d_in[2];
    float* out = (float*)d_out;

    __nv_bfloat16 *xh, *xl, *yh, *yl, *wqh, *wql, *wph, *wpl;
    cudaGetSymbolAddress((void**)&xh,  g_xh);
    cudaGetSymbolAddress((void**)&xl,  g_xl);
    cudaGetSymbolAddress((void**)&yh,  g_yh);
    cudaGetSymbolAddress((void**)&yl,  g_yl);
    cudaGetSymbolAddress((void**)&wqh, g_wqh);
    cudaGetSymbolAddress((void**)&wql, g_wql);
    cudaGetSymbolAddress((void**)&wph, g_wph);
    cudaGetSymbolAddress((void**)&wpl, g_wpl);

    cudaFuncSetAttribute(mmasync_kernel<0>, cudaFuncAttributeMaxDynamicSharedMemorySize, MM_SMEM);
    cudaFuncSetAttribute(mmasync_kernel<1>, cudaFuncAttributeMaxDynamicSharedMemorySize, MM_SMEM);
    cudaFuncSetAttribute(flash_tc_kernel,   cudaFuncAttributeMaxDynamicSharedMemorySize, FL_SMEM);
    cudaFuncSetAttribute(mmasync_kernel<0>, cudaFuncAttributePreferredSharedMemoryCarveout, 100);
    cudaFuncSetAttribute(mmasync_kernel<1>, cudaFuncAttributePreferredSharedMemoryCarveout, 100);
    cudaFuncSetAttribute(flash_tc_kernel,   cudaFuncAttributePreferredSharedMemoryCarveout, 100);

    const int n4 = MTOT * CDIM / 4;

    split_kernel<<<(n4 + 255) / 256, 256>>>(x, xh, xl, n4);

    {
        dim3 g1(C3 / 32, CDIM / 32), blk(32, 8);
        tsplit_kernel<<<g1, blk>>>(w_qkv, wqh, wql, CDIM, C3);
        dim3 g2(CDIM / 32, CDIM / 32);
        tsplit_kernel<<<g2, blk>>>(w_proj, wph, wpl, CDIM, CDIM);
    }

    {
        dim3 grid(C3 / 128, MTOT / 128);
        mmasync_kernel<1><<<grid, 256, MM_SMEM>>>(xh, xl, wqh, wql, nullptr, C3, CDIM);
    }

    {
        dim3 grid(TSEQ / 128, NHEAD, BATCH);
        flash_tc_kernel<<<grid, 256, FL_SMEM>>>();
    }

    {
        dim3 grid(CDIM / 128, MTOT / 128);
        mmasync_kernel<0><<<grid, 256, MM_SMEM>>>(yh, yl, wph, wpl, out, CDIM, CDIM);
    }
    (void)in_sizes; (void)n_in; (void)out_size;
}

// round 6
// speedup vs baseline: 4.0180x; 1.4660x over previous
#include <cuda_runtime.h>
#include <cuda_fp16.h>
#include <cstdint>

// Problem constants
#define BATCH 4
#define TSEQ  2048
#define CDIM  1024
#define NHEAD 16
#define HDIM  64
#define C3    (3*CDIM)
#define MTOT  (BATCH*TSEQ)   // 8192

// fold attention scale * log2(e) into Q so S is directly in exp2 domain
#define QSCALE 0.18033688011112042f   // 0.125 * 1.4426950408889634

// ---------------------------------------------------------------------------
// Device-global scratch (no allocation allowed)
// ---------------------------------------------------------------------------
// QKV, head-major: [part(0=Q,1=K,2=V)][b][h][t][d]; lo plane used for Q only
__device__ __align__(256) __half g_qkvh[(size_t)3 * BATCH * NHEAD * TSEQ * HDIM];
__device__ __align__(256) __half g_qkvl[(size_t)3 * BATCH * NHEAD * TSEQ * HDIM];
__device__ __align__(256) __half g_yh[(size_t)MTOT * CDIM];
__device__ __align__(256) __half g_yl[(size_t)MTOT * CDIM];
__device__ __align__(256) __half g_xh[(size_t)MTOT * CDIM];
__device__ __align__(256) __half g_xl[(size_t)MTOT * CDIM];
__device__ __align__(256) __half g_wq[(size_t)C3 * CDIM];    // transposed N x K, hi only
__device__ __align__(256) __half g_wp[(size_t)CDIM * CDIM];  // transposed N x K, hi only

// ---------------------------------------------------------------------------
// Helpers (baseline PTX only)
// ---------------------------------------------------------------------------
__device__ __forceinline__ uint32_t smem_u32(const void* p) {
    uint32_t a;
    asm("{ .reg .u64 t; cvta.to.shared.u64 t, %1; cvt.u32.u64 %0, t; }" : "=r"(a) : "l"(p));
    return a;
}
__device__ __forceinline__ void cpa16(uint32_t dst, const void* src) {
    asm volatile("cp.async.cg.shared.global [%0], [%1], 16;\n" :: "r"(dst), "l"(src));
}
#define CP_COMMIT() asm volatile("cp.async.commit_group;\n" ::: "memory")
#define CP_WAIT(n)  asm volatile("cp.async.wait_group %0;\n" :: "n"(n) : "memory")
#define SWZ128(o) ((o) ^ (((o) >> 3) & 0x70))

__device__ __forceinline__ void ldsm4(uint32_t addr, uint32_t* r) {
    asm volatile("ldmatrix.sync.aligned.m8n8.x4.shared.b16 {%0,%1,%2,%3}, [%4];"
                 : "=r"(r[0]), "=r"(r[1]), "=r"(r[2]), "=r"(r[3]) : "r"(addr));
}
__device__ __forceinline__ void ldsm4t(uint32_t addr, uint32_t* r) {
    asm volatile("ldmatrix.sync.aligned.m8n8.x4.trans.shared.b16 {%0,%1,%2,%3}, [%4];"
                 : "=r"(r[0]), "=r"(r[1]), "=r"(r[2]), "=r"(r[3]) : "r"(addr));
}
__device__ __forceinline__ void mma16816(float* d, const uint32_t* a, uint32_t b0, uint32_t b1) {
    asm volatile("mma.sync.aligned.m16n8k16.row.col.f32.f16.f16.f32 "
                 "{%0,%1,%2,%3},{%4,%5,%6,%7},{%8,%9},{%0,%1,%2,%3};"
                 : "+f"(d[0]), "+f"(d[1]), "+f"(d[2]), "+f"(d[3])
                 : "r"(a[0]), "r"(a[1]), "r"(a[2]), "r"(a[3]), "r"(b0), "r"(b1));
}
__device__ __forceinline__ uint32_t packh2(__half a, __half b) {
    __half2 t; t.x = a; t.y = b;
    return *reinterpret_cast<uint32_t*>(&t);
}

// ---------------------------------------------------------------------------
// Split fp32 -> fp16 hi/lo
// ---------------------------------------------------------------------------
__global__ void __launch_bounds__(256) split_kernel(
    const float* __restrict__ in, __half* __restrict__ hi,
    __half* __restrict__ lo, int n4)
{
    int i = blockIdx.x * 256 + threadIdx.x;
    if (i >= n4) return;
    float4 v = ((const float4*)in)[i];
    float vv[4] = {v.x, v.y, v.z, v.w};
    __half h[4], l[4];
    #pragma unroll
    for (int j = 0; j < 4; j++) {
        h[j] = __float2half(vv[j]);
        l[j] = __float2half(vv[j] - __half2float(h[j]));
    }
    ((uint32_t*)hi)[2*i]   = packh2(h[0], h[1]);
    ((uint32_t*)hi)[2*i+1] = packh2(h[2], h[3]);
    ((uint32_t*)lo)[2*i]   = packh2(l[0], l[1]);
    ((uint32_t*)lo)[2*i+1] = packh2(l[2], l[3]);
}

// ---------------------------------------------------------------------------
// Transpose weights: W (KxN fp32, row-major) -> Wt (NxK fp16, hi only)
// ---------------------------------------------------------------------------
__global__ void __launch_bounds__(256) tsplit_kernel(
    const float* __restrict__ W, __half* __restrict__ Th, int K, int N)
{
    __shared__ float t[32][33];
    int n0 = blockIdx.x * 32, k0 = blockIdx.y * 32;
    int tx = threadIdx.x, ty = threadIdx.y;
    #pragma unroll
    for (int i = 0; i < 32; i += 8)
        t[ty + i][tx] = W[(size_t)(k0 + ty + i) * N + n0 + tx];
    __syncthreads();
    #pragma unroll
    for (int i = 0; i < 32; i += 8)
        Th[(size_t)(n0 + ty + i) * K + k0 + tx] = __float2half(t[tx][ty + i]);
}

// ---------------------------------------------------------------------------
// mma.sync fp16 2-term GEMM: C(MxN) = (Ah+Al)(MxK) * B(NxK)^T
// Tile 128x128, BK=64 (128B rows, SW128), 2 stages x 3 tiles x 16KB = 96KB.
// MODE 0: fp32 C.  MODE 1: QKV head-major epilogue (Q scaled+split, K/V hi).
// ---------------------------------------------------------------------------
#define TILE_B     (128 * 128)           // 16384 B per tile
#define STAGE_B    (3 * TILE_B)          // 49152 B
#define MM_SMEM    (2 * STAGE_B)         // 98304 B

template<int MODE>
__global__ void __launch_bounds__(256, 2) mmasync_kernel(
    const __half* __restrict__ Ah, const __half* __restrict__ Al,
    const __half* __restrict__ Bh,
    float* __restrict__ C, int N, int K)
{
    extern __shared__ char smraw[];
    const uint32_t smb = smem_u32(smraw);

    const int tid  = threadIdx.x;
    const int wid  = tid >> 5, lane = tid & 31;
    const int wm   = wid & 1;
    const int wn   = wid >> 1;
    const int bm   = blockIdx.y * 128, bn = blockIdx.x * 128;
    const int l16  = lane & 15, lh = lane >> 4;

    float acc[4][4][4];
    #pragma unroll
    for (int i = 0; i < 4; i++)
        #pragma unroll
        for (int j = 0; j < 4; j++)
            #pragma unroll
            for (int k = 0; k < 4; k++) acc[i][j][k] = 0.f;

    const __half* srcs[3] = {Ah, Al, Bh};

    // fill one stage: 3 tiles x 128 rows x 8 chunks(16B) = 3072 chunks, 12/thread
    auto fill = [&](int s, int k0) {
        uint32_t sb = smb + (uint32_t)s * STAGE_B;
        #pragma unroll
        for (int t = 0; t < 3; t++) {
            const __half* src = srcs[t];
            const int rbase = (t < 2) ? bm : bn;
            uint32_t tb = sb + (uint32_t)t * TILE_B;
            #pragma unroll
            for (int i = 0; i < 4; i++) {
                int chunk = tid + i * 256;       // 0..1023
                int row = chunk >> 3, c = chunk & 7;
                cpa16(tb + SWZ128((uint32_t)(row * 128 + c * 16)),
                      src + (size_t)(rbase + row) * K + k0 + c * 8);
            }
        }
    };

    const int nch = K >> 6;   // BK = 64
    fill(0, 0); CP_COMMIT();

    for (int i = 0; i < nch; i++) {
        if (i + 1 < nch) { fill((i + 1) & 1, (i + 1) << 6); CP_COMMIT(); CP_WAIT(1); }
        else             { CP_WAIT(0); }
        __syncthreads();

        uint32_t sb = smb + (uint32_t)(i & 1) * STAGE_B;
        uint32_t Abh = sb, Abl = sb + TILE_B, Bbh = sb + 2 * TILE_B;

        #pragma unroll
        for (int kh = 0; kh < 4; kh++) {
            const uint32_t koff = (uint32_t)(kh * 32 + lh * 16);
            uint32_t ah[4][4], al[4][4];
            #pragma unroll
            for (int mt = 0; mt < 4; mt++) {
                uint32_t ro = SWZ128((uint32_t)((wm * 64 + mt * 16 + l16) * 128) + koff);
                ldsm4(Abh + ro, ah[mt]);
                ldsm4(Abl + ro, al[mt]);
            }
            uint32_t bh[2][4];
            #pragma unroll
            for (int np = 0; np < 2; np++) {
                uint32_t ro = SWZ128((uint32_t)((wn * 32 + np * 16 + l16) * 128) + koff);
                ldsm4(Bbh + ro, bh[np]);
            }
            #pragma unroll
            for (int mt = 0; mt < 4; mt++)
                #pragma unroll
                for (int nt = 0; nt < 4; nt++) {
                    const int np = nt >> 1, o = nt & 1;
                    mma16816(acc[mt][nt], ah[mt], bh[np][o], bh[np][o + 2]);
                    mma16816(acc[mt][nt], al[mt], bh[np][o], bh[np][o + 2]);
                }
        }
        __syncthreads();
    }

    const int er = lane >> 2, ec = (lane & 3) * 2;
    #pragma unroll
    for (int mt = 0; mt < 4; mt++)
        #pragma unroll
        for (int nt = 0; nt < 4; nt++) {
            int r0 = bm + wm * 64 + mt * 16 + er;
            int c0 = bn + wn * 32 + nt * 8 + ec;
            if (MODE == 0) {
                *(float2*)&C[(size_t)r0 * N + c0] =
                    make_float2(acc[mt][nt][0], acc[mt][nt][1]);
                *(float2*)&C[(size_t)(r0 + 8) * N + c0] =
                    make_float2(acc[mt][nt][2], acc[mt][nt][3]);
            } else {
                int bb = r0 >> 11, t = r0 & 2047;
                int part = c0 >> 10, rem = c0 & 1023;
                int hh = rem >> 6, d = rem & 63;
                size_t o = ((((size_t)part * BATCH + bb) * NHEAD + hh) * TSEQ + t) * HDIM + d;
                #pragma unroll
                for (int rr = 0; rr < 2; rr++) {
                    float v0 = acc[mt][nt][2 * rr + 0];
                    float v1 = acc[mt][nt][2 * rr + 1];
                    size_t oo = o + (size_t)rr * 8 * HDIM;
                    if (part == 0) {
                        v0 *= QSCALE; v1 *= QSCALE;
                        __half h0 = __float2half(v0), h1 = __float2half(v1);
                        *(uint32_t*)&g_qkvh[oo] = packh2(h0, h1);
                        *(uint32_t*)&g_qkvl[oo] = packh2(
                            __float2half(v0 - __half2float(h0)),
                            __float2half(v1 - __half2float(h1)));
                    } else {
                        *(uint32_t*)&g_qkvh[oo] = packh2(__float2half(v0), __float2half(v1));
                    }
                }
            }
        }
}

// ---------------------------------------------------------------------------
// Tensor-core flash attention (causal), fp16 2-term, Bq=128, Bk=64, D=64.
// smem: Qh(16K) Ql(16K) + 2 stages x {Kh,Vh} (8K each) = 64KB, SW128.
// ---------------------------------------------------------------------------
#define FL_SMEM (64 * 1024)

__global__ void __launch_bounds__(256, 2) flash_tc_kernel()
{
    extern __shared__ char smraw[];
    const uint32_t S = smem_u32(smraw);
    const int tid = threadIdx.x, w = tid >> 5, lane = tid & 31;
    const int l16 = lane & 15, lh = lane >> 4;
    const int b = blockIdx.z, h = blockIdx.y;
    const int qt = (int)(gridDim.x - 1 - blockIdx.x);   // heaviest first
    const int n_kt = 2 * qt + 2;

    const uint32_t Qh_s = S, Ql_s = S + 16384;
    const uint32_t stg0 = S + 32768;    // stage s at stg0 + s*16384

    const size_t head = (((size_t)b) * NHEAD + h) * TSEQ * HDIM;
    const size_t HSZ  = (size_t)BATCH * NHEAD * TSEQ * HDIM;
    const __half* qh = g_qkvh + head;
    const __half* ql = g_qkvl + head;
    const __half* kh = g_qkvh + HSZ + head;
    const __half* vh = g_qkvh + 2 * HSZ + head;

    {
        #pragma unroll
        for (int i = 0; i < 8; i++) {
            int idx = tid + i * 256;
            int mtx = idx >> 10, row = (idx >> 3) & 127, c = idx & 7;
            const __half* src = (mtx ? ql : qh) + (size_t)(qt * 128 + row) * HDIM + c * 8;
            cpa16((mtx ? Ql_s : Qh_s) + SWZ128((uint32_t)(row * 128 + c * 16)), src);
        }
    }
    auto fillkv = [&](int s, int kt) {
        uint32_t sb = stg0 + (uint32_t)s * 16384u;
        const __half* bases[2] = {kh, vh};
        #pragma unroll
        for (int i = 0; i < 4; i++) {
            int idx = tid + i * 256;                // 0..1023
            int mtx = idx >> 9, row = (idx >> 3) & 63, c = idx & 7;
            cpa16(sb + (uint32_t)mtx * 8192u + SWZ128((uint32_t)(row * 128 + c * 16)),
                  bases[mtx] + (size_t)(kt * 64 + row) * HDIM + c * 8);
        }
    };

    fillkv(0, 0); CP_COMMIT();
    if (n_kt > 1) { fillkv(1, 1); CP_COMMIT(); }

    float m0 = -1e30f, m1 = -1e30f, l0 = 0.f, l1 = 0.f;
    float o[8][4];
    #pragma unroll
    for (int j = 0; j < 8; j++)
        #pragma unroll
        for (int e = 0; e < 4; e++) o[j][e] = 0.f;

    for (int kt = 0; kt < n_kt; kt++) {
        if (kt + 1 < n_kt) { CP_WAIT(1); } else { CP_WAIT(0); }
        __syncthreads();

        const uint32_t sb   = stg0 + (uint32_t)(kt & 1) * 16384u;
        const uint32_t Kh_s = sb, Vh_s = sb + 8192;

        // ---- S = Q K^T (2-term: (Qh+Ql)·Kh) ----
        float s[8][4];
        #pragma unroll
        for (int j = 0; j < 8; j++)
            #pragma unroll
            for (int e = 0; e < 4; e++) s[j][e] = 0.f;

        #pragma unroll
        for (int kk = 0; kk < 4; kk++) {
            const uint32_t koff = (uint32_t)(kk * 32 + lh * 16);
            uint32_t qf[4], qlf[4];
            ldsm4(Qh_s + SWZ128((uint32_t)((w * 16 + l16) * 128) + koff), qf);
            ldsm4(Ql_s + SWZ128((uint32_t)((w * 16 + l16) * 128) + koff), qlf);
            #pragma unroll
            for (int g = 0; g < 4; g++) {
                uint32_t kf[4];
                ldsm4(Kh_s + SWZ128((uint32_t)((g * 16 + l16) * 128) + koff), kf);
                mma16816(s[2 * g],     qf,  kf[0], kf[2]);
                mma16816(s[2 * g],     qlf, kf[0], kf[2]);
                mma16816(s[2 * g + 1], qf,  kf[1], kf[3]);
                mma16816(s[2 * g + 1], qlf, kf[1], kf[3]);
            }
        }

        // ---- causal mask ----
        const int row0 = qt * 128 + w * 16 + (lane >> 2);
        if (kt * 64 + 63 > qt * 128 + w * 16) {
            #pragma unroll
            for (int j = 0; j < 8; j++) {
                int colb = kt * 64 + j * 8 + (lane & 3) * 2;
                if (colb + 0 > row0)     s[j][0] = -1e30f;
                if (colb + 1 > row0)     s[j][1] = -1e30f;
                if (colb + 0 > row0 + 8) s[j][2] = -1e30f;
                if (colb + 1 > row0 + 8) s[j][3] = -1e30f;
            }
        }

        // ---- online softmax (exp2 domain) ----
        float mx0 = -1e30f, mx1 = -1e30f;
        #pragma unroll
        for (int j = 0; j < 8; j++) {
            mx0 = fmaxf(mx0, fmaxf(s[j][0], s[j][1]));
            mx1 = fmaxf(mx1, fmaxf(s[j][2], s[j][3]));
        }
        mx0 = fmaxf(mx0, __shfl_xor_sync(0xffffffffu, mx0, 1));
        mx0 = fmaxf(mx0, __shfl_xor_sync(0xffffffffu, mx0, 2));
        mx1 = fmaxf(mx1, __shfl_xor_sync(0xffffffffu, mx1, 1));
        mx1 = fmaxf(mx1, __shfl_xor_sync(0xffffffffu, mx1, 2));
        float nm0 = fmaxf(m0, mx0), nm1 = fmaxf(m1, mx1);
        float c0 = exp2f(m0 - nm0), c1 = exp2f(m1 - nm1);
        m0 = nm0; m1 = nm1;
        float sum0 = 0.f, sum1 = 0.f;
        #pragma unroll
        for (int j = 0; j < 8; j++) {
            s[j][0] = exp2f(s[j][0] - m0);
            s[j][1] = exp2f(s[j][1] - m0);
            s[j][2] = exp2f(s[j][2] - m1);
            s[j][3] = exp2f(s[j][3] - m1);
            sum0 += s[j][0] + s[j][1];
            sum1 += s[j][2] + s[j][3];
        }
        sum0 += __shfl_xor_sync(0xffffffffu, sum0, 1);
        sum0 += __shfl_xor_sync(0xffffffffu, sum0, 2);
        sum1 += __shfl_xor_sync(0xffffffffu, sum1, 1);
        sum1 += __shfl_xor_sync(0xffffffffu, sum1, 2);
        l0 = l0 * c0 + sum0;
        l1 = l1 * c1 + sum1;
        #pragma unroll
        for (int j = 0; j < 8; j++) {
            o[j][0] *= c0; o[j][1] *= c0; o[j][2] *= c1; o[j][3] *= c1;
        }

        // ---- O += P V (2-term: (Ph+Pl)·Vh) ----
        #pragma unroll
        for (int kk = 0; kk < 4; kk++) {
            uint32_t pa[4], pb[4];
            #pragma unroll
            for (int half = 0; half < 2; half++) {
                const int f = 2 * kk + half;
                __half h0 = __float2half(s[f][0]);
                __half h1 = __float2half(s[f][1]);
                __half h2 = __float2half(s[f][2]);
                __half h3 = __float2half(s[f][3]);
                pa[2 * half + 0] = packh2(h0, h1);
                pa[2 * half + 1] = packh2(h2, h3);
                pb[2 * half + 0] = packh2(
                    __float2half(s[f][0] - __half2float(h0)),
                    __float2half(s[f][1] - __half2float(h1)));
                pb[2 * half + 1] = packh2(
                    __float2half(s[f][2] - __half2float(h2)),
                    __float2half(s[f][3] - __half2float(h3)));
            }
            #pragma unroll
            for (int g = 0; g < 4; g++) {
                uint32_t vf[4];
                uint32_t ro = SWZ128((uint32_t)((kk * 16 + l16) * 128 + g * 32) + (uint32_t)(lh * 16));
                ldsm4t(Vh_s + ro, vf);
                mma16816(o[2 * g],     pa, vf[0], vf[1]);
                mma16816(o[2 * g],     pb, vf[0], vf[1]);
                mma16816(o[2 * g + 1], pa, vf[2], vf[3]);
                mma16816(o[2 * g + 1], pb, vf[2], vf[3]);
            }
        }

        __syncthreads();
        if (kt + 2 < n_kt) { fillkv(kt & 1, kt + 2); CP_COMMIT(); }
    }

    // ---- epilogue: normalize, split to fp16 hi/lo, write y ----
    const float inv0 = 1.f / l0, inv1 = 1.f / l1;
    const int r0 = qt * 128 + w * 16 + (lane >> 2);
    const int t0 = r0, t1 = r0 + 8;
    #pragma unroll
    for (int j = 0; j < 8; j++) {
        int d = j * 8 + (lane & 3) * 2;
        size_t o0 = ((size_t)b * TSEQ + t0) * CDIM + h * HDIM + d;
        size_t o1 = ((size_t)b * TSEQ + t1) * CDIM + h * HDIM + d;
        float y0 = o[j][0] * inv0, y1 = o[j][1] * inv0;
        float y2 = o[j][2] * inv1, y3 = o[j][3] * inv1;
        __half h0 = __float2half(y0), h1 = __float2half(y1);
        __half h2 = __float2half(y2), h3 = __float2half(y3);
        *(uint32_t*)&g_yh[o0] = packh2(h0, h1);
        *(uint32_t*)&g_yh[o1] = packh2(h2, h3);
        *(uint32_t*)&g_yl[o0] = packh2(
            __float2half(y0 - __half2float(h0)),
            __float2half(y1 - __half2float(h1)));
        *(uint32_t*)&g_yl[o1] = packh2(
            __float2half(y2 - __half2float(h2)),
            __float2half(y3 - __half2float(h3)));
    }
}

// ---------------------------------------------------------------------------
extern "C" void kernel_launch(void* const* d_in, const int* in_sizes, int n_in,
                              void* d_out, int out_size)
{
    const float* x      = (const float*)d_in[0];
    const float* w_qkv  = (const float*)d_in[1];
    const float* w_proj = (const float*)d_in[2];
    float* out = (float*)d_out;

    __half *xh, *xl, *yh, *yl, *wq, *wp;
    cudaGetSymbolAddress((void**)&xh, g_xh);
    cudaGetSymbolAddress((void**)&xl, g_xl);
    cudaGetSymbolAddress((void**)&yh, g_yh);
    cudaGetSymbolAddress((void**)&yl, g_yl);
    cudaGetSymbolAddress((void**)&wq, g_wq);
    cudaGetSymbolAddress((void**)&wp, g_wp);

    cudaFuncSetAttribute(mmasync_kernel<0>, cudaFuncAttributeMaxDynamicSharedMemorySize, MM_SMEM);
    cudaFuncSetAttribute(mmasync_kernel<1>, cudaFuncAttributeMaxDynamicSharedMemorySize, MM_SMEM);
    cudaFuncSetAttribute(flash_tc_kernel,   cudaFuncAttributeMaxDynamicSharedMemorySize, FL_SMEM);
    cudaFuncSetAttribute(mmasync_kernel<0>, cudaFuncAttributePreferredSharedMemoryCarveout, 100);
    cudaFuncSetAttribute(mmasync_kernel<1>, cudaFuncAttributePreferredSharedMemoryCarveout, 100);
    cudaFuncSetAttribute(flash_tc_kernel,   cudaFuncAttributePreferredSharedMemoryCarveout, 100);

    const int n4 = MTOT * CDIM / 4;

    // 1) split X -> fp16 hi/lo
    split_kernel<<<(n4 + 255) / 256, 256>>>(x, xh, xl, n4);

    // 2) transpose weights (fp16 hi only)
    {
        dim3 g1(C3 / 32, CDIM / 32), blk(32, 8);
        tsplit_kernel<<<g1, blk>>>(w_qkv, wq, CDIM, C3);
        dim3 g2(CDIM / 32, CDIM / 32);
        tsplit_kernel<<<g2, blk>>>(w_proj, wp, CDIM, CDIM);
    }

    // 3) QKV GEMM with head-major epilogue (Q pre-scaled + split)
    {
        dim3 grid(C3 / 128, MTOT / 128);
        mmasync_kernel<1><<<grid, 256, MM_SMEM>>>(xh, xl, wq, nullptr, C3, CDIM);
    }

    // 4) tensor-core flash attention -> g_yh/g_yl
    {
        dim3 grid(TSEQ / 128, NHEAD, BATCH);
        flash_tc_kernel<<<grid, 256, FL_SMEM>>>();
    }

    // 5) proj GEMM: out = (Yh+Yl) @ Wp (fp32 epilogue)
    {
        dim3 grid(CDIM / 128, MTOT / 128);
        mmasync_kernel<0><<<grid, 256, MM_SMEM>>>(yh, yl, wp, out, CDIM, CDIM);
    }
    (void)in_sizes; (void)n_in; (void)out_size;
}